// round 10
// baseline (speedup 1.0000x reference)
#include <cuda_runtime.h>
#include <cuda_fp16.h>
#include <math.h>
#include <float.h>

// B=1, C_IN=32, D_OUT=32, P=2048, N=10, A=12
typedef unsigned long long ull;

// ---------------- packed f32x2 helpers (sm_103a) ---------------------------
__device__ __forceinline__ ull f2pk(float lo, float hi) {
    ull r; asm("mov.b64 %0,{%1,%2};" : "=l"(r) : "f"(lo), "f"(hi)); return r;
}
__device__ __forceinline__ void f2up(ull v, float& lo, float& hi) {
    asm("mov.b64 {%0,%1},%2;" : "=f"(lo), "=f"(hi) : "l"(v));
}
__device__ __forceinline__ ull ffma2(ull a, ull b, ull c) {
    ull d; asm("fma.rn.f32x2 %0,%1,%2,%3;" : "=l"(d) : "l"(a), "l"(b), "l"(c)); return d;
}
__device__ __forceinline__ ull fmul2(ull a, ull b) {
    ull d; asm("mul.rn.f32x2 %0,%1,%2;" : "=l"(d) : "l"(a), "l"(b)); return d;
}

// ---------------- device scratch ------------------------------------------
__device__ float g_ICO[108];                   // VER[r][i][j] floats (for k_ka)
__device__ float g_KDNT[12 * 3 * 32 * 12];     // [k][i][d][r]
__device__ float g_W2[416 * 96];               // [dk][c*3+j]
__device__ float g_BIASF[416];                 // [dk]
__device__ float g_FMP[1024 * 192];            // [pair][c*3+i][2]  (pair = p>>1)
__device__ __half g_KAH2[2048 * 12 * 32 * 12]; // [q][k][d][r]  fp16, 18.9MB
__device__ float g_CEN[32 * 2048 * 12];        // [d][p][r] center (k==12), fp32

// ---------------- icosa constants: FP64, sqrt-only (no trig) ---------------
__device__ __forceinline__ void icosa_vertex(int r, double* u) {
    const double phi = (1.0 + sqrt(5.0)) * 0.5;
    int ia = r / 6, ib = (r / 3) % 2, t = r % 3;
    double a = ia ? -1.0 : 1.0;
    double b = ib ? -phi : phi;
    double v0, v1, v2;
    if (t == 0)      { v0 = 0.0; v1 = a;   v2 = b; }
    else if (t == 1) { v0 = a;   v1 = b;   v2 = 0.0; }
    else             { v0 = b;   v1 = 0.0; v2 = a; }
    double inv = 1.0 / sqrt(v0*v0 + v1*v1 + v2*v2);
    u[0] = v0*inv; u[1] = v1*inv; u[2] = v2*inv;
}
__device__ __forceinline__ double cos5(int m) {
    const double c1 = 0.30901699437494745;   // cos 72
    const double c2 = -0.8090169943749475;   // cos 144
    return (m == 0) ? 1.0 : (m == 1 || m == 4) ? c1 : c2;
}
__device__ __forceinline__ double sin5(int m) {
    const double s1 = 0.9510565162951535;    // sin 72
    const double s2 = 0.5877852522924731;    // sin 144
    return (m == 0) ? 0.0 : (m == 1) ? s1 : (m == 2) ? s2 : (m == 3) ? -s2 : -s1;
}
__device__ __forceinline__ float ver_elem(int tid) {
    int r = tid / 9, e = tid % 9, i = e / 3, j = e % 3;
    double u[3]; icosa_vertex(r, u);
    double c = u[2];
    double axx = -u[1], axy = u[0];
    double s = sqrt(axx*axx + axy*axy);
    double R[3][3];
    if (s < 1e-9) {
        for (int a = 0; a < 3; a++) for (int b = 0; b < 3; b++) R[a][b] = 0.0;
        R[0][0] = 1.0; R[1][1] = (c > 0) ? 1.0 : -1.0; R[2][2] = (c > 0) ? 1.0 : -1.0;
    } else {
        double kx = axx / s, ky = axy / s;
        double K[3][3] = {{0, 0, ky}, {0, 0, -kx}, {-ky, kx, 0}};
        double KK[3][3];
        for (int a = 0; a < 3; a++)
            for (int b = 0; b < 3; b++) {
                double acc = 0.0;
                for (int q = 0; q < 3; q++) acc += K[a][q]*K[q][b];
                KK[a][b] = acc;
            }
        for (int a = 0; a < 3; a++)
            for (int b = 0; b < 3; b++)
                R[a][b] = (a == b ? 1.0 : 0.0) + s*K[a][b] + (1.0 - c)*KK[a][b];
    }
    return (float)R[i][j];
}

// ---------------- kernel 1: fused fm (blocks 0-255) + weight prep (256-327)
__global__ void __launch_bounds__(256) k_fmprep(const float* __restrict__ fmap,
                                                const float* __restrict__ fcw,
                                                const float* __restrict__ W,
                                                const float* __restrict__ bias,
                                                const float* __restrict__ dirs,
                                                float* __restrict__ fm_out) {
    int tid = threadIdx.x;
    if (blockIdx.x < 256) {
        // ---- fm path: 8 warps x 1 point each ----
        __shared__ float FCT[32*33];
        __shared__ float Xs[8][384];
        __shared__ float VSs[36];
        for (int i = tid; i < 1024; i += 256) {
            int r = i >> 5, cc = i & 31;
            FCT[cc*33 + r] = fcw[i];
        }
        if (tid < 12) {
            double u[3]; icosa_vertex(tid, u);
            VSs[tid*3+0] = (float)u[0];
            VSs[tid*3+1] = (float)u[1];
            VSs[tid*3+2] = (float)u[2];
        }
        int w = tid >> 5, lane = tid & 31;
        int p = blockIdx.x*8 + w;
        const float4* src = (const float4*)&fmap[((size_t)lane*2048 + p)*12];
        float4 x0 = src[0], x1 = src[1], x2 = src[2];
        Xs[w][0*32+lane] = x0.x;  Xs[w][1*32+lane]  = x0.y;
        Xs[w][2*32+lane] = x0.z;  Xs[w][3*32+lane]  = x0.w;
        Xs[w][4*32+lane] = x1.x;  Xs[w][5*32+lane]  = x1.y;
        Xs[w][6*32+lane] = x1.z;  Xs[w][7*32+lane]  = x1.w;
        Xs[w][8*32+lane] = x2.x;  Xs[w][9*32+lane]  = x2.y;
        Xs[w][10*32+lane] = x2.z; Xs[w][11*32+lane] = x2.w;
        __syncthreads();

        float L[12];
#pragma unroll
        for (int a = 0; a < 12; a++) L[a] = 0.f;
#pragma unroll
        for (int cc = 0; cc < 32; cc++) {
            float fc = FCT[cc*33 + lane];
#pragma unroll
            for (int a = 0; a < 12; a++) L[a] += Xs[w][a*32+cc] * fc;
        }
        float mx = L[0];
#pragma unroll
        for (int a = 1; a < 12; a++) mx = fmaxf(mx, L[a]);
        float e[12], s = 0.f;
#pragma unroll
        for (int a = 0; a < 12; a++) { e[a] = expf(L[a] - mx); s += e[a]; }
        float inv = 1.f / s;
        float f0 = 0.f, f1 = 0.f, f2 = 0.f;
#pragma unroll
        for (int a = 0; a < 12; a++) {
            float y = e[a] * inv * Xs[w][a*32+lane];
            f0 += y * VSs[a*3+0];
            f1 += y * VSs[a*3+1];
            f2 += y * VSs[a*3+2];
        }
        float* fp = &g_FMP[((size_t)(p >> 1)*96 + lane*3)*2 + (p & 1)];
        fp[0] = f0; fp[2] = f1; fp[4] = f2;
        fm_out[((size_t)lane*2048 + p)*3 + 0] = f0;
        fm_out[((size_t)lane*2048 + p)*3 + 1] = f1;
        fm_out[((size_t)lane*2048 + p)*3 + 2] = f2;
    } else {
        // ---- weight prep path ----
        __shared__ float SYMR[45];
        __shared__ float VER[108];
        if (tid < 45) {
            int m = tid / 9, e = tid % 9, i = e / 3, j = e % 3;
            double ct = cos5(m), st = sin5(m);
            double R[3][3] = {{ct, -st, 0.0}, {st, ct, 0.0}, {0.0, 0.0, 1.0}};
            SYMR[tid] = (float)R[i][j];
        }
        if (tid < 108) {
            float v = ver_elem(tid);
            VER[tid] = v;
            if (blockIdx.x == 256) g_ICO[tid] = v;   // publish for k_ka
        }
        __syncthreads();
        int t = (blockIdx.x - 256) * 256 + tid;
        if (t < 4608) {
            int d = t / 144, k = (t / 12) % 12, r = t % 12;
            float vv[3];
            if (k == 0)      { vv[0] = 0.f; vv[1] = 0.f; vv[2] = 1.f; }
            else if (k == 1) { vv[0] = 0.f; vv[1] = 0.f; vv[2] = -1.f; }
            else {
                int kk = (k - 2) / 5, m = (k - 2) % 5;
                float d0 = dirs[d*6 + kk*3 + 0];
                float d1 = dirs[d*6 + kk*3 + 1];
                float d2 = dirs[d*6 + kk*3 + 2];
                float nrm = sqrtf(d0*d0 + d1*d1 + d2*d2);
                float inv = 1.f / fmaxf(nrm, 1e-12f);
                d0 *= inv; d1 *= inv; d2 *= inv;
                for (int i = 0; i < 3; i++)
                    vv[i] = SYMR[m*9+i*3+0]*d0 + SYMR[m*9+i*3+1]*d1 + SYMR[m*9+i*3+2]*d2;
            }
            for (int i = 0; i < 3; i++) {
                float o = VER[r*9+i*3+0]*vv[0] + VER[r*9+i*3+1]*vv[1] + VER[r*9+i*3+2]*vv[2];
                g_KDNT[((k*3 + i)*32 + d)*12 + r] = o;
            }
        } else if (t < 4608 + 13312) {
            int id = t - 4608;
            int dk = id / 32, c = id % 32;
            int d = dk / 13, k = dk % 13;
            const float* wr = W + (d*32 + c)*9;
            float wf[3];
            if (k == 0)       { wf[0] = 0.f; wf[1] = 0.f; wf[2] = wr[0]; }
            else if (k == 1)  { wf[0] = 0.f; wf[1] = 0.f; wf[2] = -wr[1]; }
            else if (k == 12) { wf[0] = 0.f; wf[1] = 0.f; wf[2] = wr[8]; }
            else {
                int kk = (k - 2) / 5, m = (k - 2) % 5;
                float w0 = wr[2 + kk*3 + 0], w1 = wr[2 + kk*3 + 1], w2 = wr[2 + kk*3 + 2];
                for (int i = 0; i < 3; i++)
                    wf[i] = SYMR[m*9+i*3+0]*w0 + SYMR[m*9+i*3+1]*w1 + SYMR[m*9+i*3+2]*w2;
            }
            g_W2[dk*96 + c*3 + 0] = wf[0];
            g_W2[dk*96 + c*3 + 1] = wf[1];
            g_W2[dk*96 + c*3 + 2] = wf[2];
        } else if (t < 4608 + 13312 + 416) {
            int dk = t - (4608 + 13312);
            int d = dk / 13, k = dk % 13;
            int col = (k == 0) ? 0 : (k == 1) ? 1 : (k <= 6) ? 2 : (k <= 11) ? 3 : 4;
            g_BIASF[dk] = bias[d*5 + col];
        }
    }
}

// ---------------- kernel 2: ka — one k x 32 d x 32 p per block -------------
// 256 thr = 32 d x 8 ps; NO min-blocks clause (avoid register spills)
__global__ void __launch_bounds__(256) k_ka() {
    __shared__ float  Ws[32*97];    // [d][c*3+j]
    __shared__ ull    Fp[16][98];   // [pair][c*3+i] = {fm[even], fm[odd]}
    __shared__ float2 verd[108];
    __shared__ float2 biasd[32];
    __shared__ __half Hs[32*384];   // [pl][d*12+r]  768B per point row
    int k  = blockIdx.x;            // 0..12
    int p0 = blockIdx.y * 32;
    int tid = threadIdx.x;

    for (int i = tid; i < 32*96; i += 256) {
        int dd = i / 96, q = i % 96;
        Ws[dd*97 + q] = g_W2[(dd*13 + k)*96 + q];
    }
    {
        const float4* src = (const float4*)&g_FMP[(size_t)(p0 >> 1) * 192];
        for (int i = tid; i < 16*48; i += 256)
            ((float4*)&Fp[i / 48][0])[i % 48] = src[i];
    }
    if (tid < 108) { float v = g_ICO[tid]; verd[tid] = make_float2(v, v); }
    if (tid < 32)  { float bv = g_BIASF[tid*13 + k]; biasd[tid] = make_float2(bv, bv); }
    __syncthreads();

    int d  = tid & 31;
    int ps = tid >> 5;              // 0..7: pairs 2ps, 2ps+1 = points p0+4ps..+3
    const float* wrow = &Ws[d*97];
    const ull* fA = Fp[2*ps];
    const ull* fB = Fp[2*ps + 1];

    ull GA[9], GB[9];
#pragma unroll
    for (int q = 0; q < 9; q++) { GA[q] = 0ULL; GB[q] = 0ULL; }

#pragma unroll 4
    for (int cp = 0; cp < 16; cp++) {   // c = 2cp, 2cp+1
        float we0 = wrow[6*cp+0], we1 = wrow[6*cp+1], we2 = wrow[6*cp+2];
        float wo0 = wrow[6*cp+3], wo1 = wrow[6*cp+4], wo2 = wrow[6*cp+5];
        ull We0 = f2pk(we0, we0), We1 = f2pk(we1, we1), We2 = f2pk(we2, we2);
        ull Wo0 = f2pk(wo0, wo0), Wo1 = f2pk(wo1, wo1), Wo2 = f2pk(wo2, wo2);
        ulonglong2 aA = *(const ulonglong2*)&fA[6*cp];       // f0e, f1e
        ulonglong2 aB = *(const ulonglong2*)&fA[6*cp+2];     // f2e, f0o
        ulonglong2 aC = *(const ulonglong2*)&fA[6*cp+4];     // f1o, f2o
        ulonglong2 bA = *(const ulonglong2*)&fB[6*cp];
        ulonglong2 bB = *(const ulonglong2*)&fB[6*cp+2];
        ulonglong2 bC = *(const ulonglong2*)&fB[6*cp+4];
        // even c
        GA[0] = ffma2(We0, aA.x, GA[0]); GA[1] = ffma2(We0, aA.y, GA[1]); GA[2] = ffma2(We0, aB.x, GA[2]);
        GA[3] = ffma2(We1, aA.x, GA[3]); GA[4] = ffma2(We1, aA.y, GA[4]); GA[5] = ffma2(We1, aB.x, GA[5]);
        GA[6] = ffma2(We2, aA.x, GA[6]); GA[7] = ffma2(We2, aA.y, GA[7]); GA[8] = ffma2(We2, aB.x, GA[8]);
        GB[0] = ffma2(We0, bA.x, GB[0]); GB[1] = ffma2(We0, bA.y, GB[1]); GB[2] = ffma2(We0, bB.x, GB[2]);
        GB[3] = ffma2(We1, bA.x, GB[3]); GB[4] = ffma2(We1, bA.y, GB[4]); GB[5] = ffma2(We1, bB.x, GB[5]);
        GB[6] = ffma2(We2, bA.x, GB[6]); GB[7] = ffma2(We2, bA.y, GB[7]); GB[8] = ffma2(We2, bB.x, GB[8]);
        // odd c
        GA[0] = ffma2(Wo0, aB.y, GA[0]); GA[1] = ffma2(Wo0, aC.x, GA[1]); GA[2] = ffma2(Wo0, aC.y, GA[2]);
        GA[3] = ffma2(Wo1, aB.y, GA[3]); GA[4] = ffma2(Wo1, aC.x, GA[4]); GA[5] = ffma2(Wo1, aC.y, GA[5]);
        GA[6] = ffma2(Wo2, aB.y, GA[6]); GA[7] = ffma2(Wo2, aC.x, GA[7]); GA[8] = ffma2(Wo2, aC.y, GA[8]);
        GB[0] = ffma2(Wo0, bB.y, GB[0]); GB[1] = ffma2(Wo0, bC.x, GB[1]); GB[2] = ffma2(Wo0, bC.y, GB[2]);
        GB[3] = ffma2(Wo1, bB.y, GB[3]); GB[4] = ffma2(Wo1, bC.x, GB[4]); GB[5] = ffma2(Wo1, bC.y, GB[5]);
        GB[6] = ffma2(Wo2, bB.y, GB[6]); GB[7] = ffma2(Wo2, bC.x, GB[7]); GB[8] = ffma2(Wo2, bC.y, GB[8]);
    }

    ull bias2 = *(const ull*)&biasd[d];
    int pl0 = ps*4;                 // pair A -> points pl0, pl0+1; pair B -> +2,+3

#pragma unroll
    for (int g4 = 0; g4 < 3; g4++) {
        ull oA[4], oB[4];
#pragma unroll
        for (int rr = 0; rr < 4; rr++) {
            int r = g4*4 + rr;
            ull sA = bias2, sB = bias2;
#pragma unroll
            for (int i = 0; i < 3; i++)
#pragma unroll
                for (int j = 0; j < 3; j++) {
                    ull v = *(const ull*)&verd[r*9 + i*3 + j];
                    sA = ffma2(v, GA[j*3 + i], sA);
                    sB = ffma2(v, GB[j*3 + i], sB);
                }
            oA[rr] = sA; oB[rr] = sB;
        }
        float a0l,a0h,a1l,a1h,a2l,a2h,a3l,a3h;
        float b0l,b0h,b1l,b1h,b2l,b2h,b3l,b3h;
        f2up(oA[0], a0l, a0h); f2up(oA[1], a1l, a1h);
        f2up(oA[2], a2l, a2h); f2up(oA[3], a3l, a3h);
        f2up(oB[0], b0l, b0h); f2up(oB[1], b1l, b1h);
        f2up(oB[2], b2l, b2h); f2up(oB[3], b3l, b3h);
        if (k == 12) {
            *(float4*)&g_CEN[((size_t)d*2048 + p0 + pl0 + 0)*12 + g4*4] = make_float4(a0l, a1l, a2l, a3l);
            *(float4*)&g_CEN[((size_t)d*2048 + p0 + pl0 + 1)*12 + g4*4] = make_float4(a0h, a1h, a2h, a3h);
            *(float4*)&g_CEN[((size_t)d*2048 + p0 + pl0 + 2)*12 + g4*4] = make_float4(b0l, b1l, b2l, b3l);
            *(float4*)&g_CEN[((size_t)d*2048 + p0 + pl0 + 3)*12 + g4*4] = make_float4(b0h, b1h, b2h, b3h);
        } else {
            __half2 hA0 = __floats2half2_rn(a0l, a1l), hA1 = __floats2half2_rn(a2l, a3l);
            __half2 hB0 = __floats2half2_rn(a0h, a1h), hB1 = __floats2half2_rn(a2h, a3h);
            __half2 hC0 = __floats2half2_rn(b0l, b1l), hC1 = __floats2half2_rn(b2l, b3l);
            __half2 hD0 = __floats2half2_rn(b0h, b1h), hD1 = __floats2half2_rn(b2h, b3h);
            *(ull*)&Hs[(pl0+0)*384 + d*12 + g4*4] = ((ull)*(unsigned*)&hA1 << 32) | *(unsigned*)&hA0;
            *(ull*)&Hs[(pl0+1)*384 + d*12 + g4*4] = ((ull)*(unsigned*)&hB1 << 32) | *(unsigned*)&hB0;
            *(ull*)&Hs[(pl0+2)*384 + d*12 + g4*4] = ((ull)*(unsigned*)&hC1 << 32) | *(unsigned*)&hC0;
            *(ull*)&Hs[(pl0+3)*384 + d*12 + g4*4] = ((ull)*(unsigned*)&hD1 << 32) | *(unsigned*)&hD0;
        }
    }

    if (k < 12) {
        __syncthreads();
        // dense write-out: 32 rows x 768B, coalesced uint4
        const uint4* hsrc = (const uint4*)Hs;
        uint4* dst = (uint4*)g_KAH2;
        int kbase = k * 48;             // uint4 offset within point row (576/pt)
        for (int i = tid; i < 1536; i += 256) {
            int pl = i / 48, off = i % 48;
            dst[(size_t)(p0 + pl)*576 + kbase + off] = hsrc[pl*48 + off];
        }
    }
}

// ---------------- kernel 3: theta + gather + max_n + sum_k + center -------
// block = 4 points x 96 (d,rg); packed f32x2 theta, scalar accumulators
__global__ void __launch_bounds__(384, 2) k_final(const int* __restrict__ nbr,
                                                  const float* __restrict__ verts,
                                                  float* __restrict__ out) {
    __shared__ float2 nddup[4][10][3];   // lane-duplicated ndn
    __shared__ int qoffs[4][10];
    int tid = threadIdx.x;
    if (tid < 40) {
        int pp2 = tid / 10, n = tid % 10;
        int p2 = blockIdx.x*4 + pp2;
        int q = nbr[p2*10 + n];
        qoffs[pp2][n] = q * 9216;
        float dx = verts[q*3+0] - verts[p2*3+0];
        float dy = verts[q*3+1] - verts[p2*3+1];
        float dz = verts[q*3+2] - verts[p2*3+2];
        float nrm = sqrtf(dx*dx + dy*dy + dz*dz);
        float inv = 1.f / fmaxf(nrm, 1e-12f);
        nddup[pp2][n][0] = make_float2(dx*inv, dx*inv);
        nddup[pp2][n][1] = make_float2(dy*inv, dy*inv);
        nddup[pp2][n][2] = make_float2(dz*inv, dz*inv);
    }
    __syncthreads();
    int pp = tid / 96;
    int u  = tid % 96;
    int d  = u / 3, rg = u % 3;
    int p  = blockIdx.x*4 + pp;

    int qb[10];
#pragma unroll
    for (int n = 0; n < 10; n++) qb[n] = qoffs[pp][n];
    const ull* ndp = (const ull*)&nddup[pp][0][0];   // [n*3 + i]

    float4 a4 = ((const float4*)&g_CEN[((size_t)d*2048 + p)*12])[rg];
    float acc0 = a4.x, acc1 = a4.y, acc2 = a4.z, acc3 = a4.w;

    const char* base = ((const char*)g_KAH2) + (size_t)d*24 + rg*8;
    const __half2 zero2 = __half2half2(__ushort_as_half(0));

#pragma unroll 1
    for (int k = 0; k < 12; k++) {
        const float* ktb = &g_KDNT[k*1152 + d*12 + rg*4];
        float4 c0 = __ldg((const float4*)(ktb + 0));
        float4 c1 = __ldg((const float4*)(ktb + 384));
        float4 c2 = __ldg((const float4*)(ktb + 768));
        ull A01 = f2pk(c0.x, c0.y), A23 = f2pk(c0.z, c0.w);
        ull B01 = f2pk(c1.x, c1.y), B23 = f2pk(c1.z, c1.w);
        ull C01 = f2pk(c2.x, c2.y), C23 = f2pk(c2.z, c2.w);
        const char* kbase = base + k*768;

        __half2 m01, m23;
#pragma unroll
        for (int n = 0; n < 10; n++) {
            ull n0 = ndp[n*3+0], n1 = ndp[n*3+1], n2 = ndp[n*3+2];
            ull t01 = ffma2(A01, n0, ffma2(B01, n1, fmul2(C01, n2)));
            ull t23 = ffma2(A23, n0, ffma2(B23, n1, fmul2(C23, n2)));
            float lo, hi;
            f2up(t01, lo, hi);
            __half2 h01 = __hmax2(__floats2half2_rn(lo, hi), zero2);
            f2up(t23, lo, hi);
            __half2 h23 = __hmax2(__floats2half2_rn(lo, hi), zero2);
            uint2 g = *(const uint2*)(kbase + qb[n]);
            __half2 v01 = __hmul2(h01, *(__half2*)&g.x);
            __half2 v23 = __hmul2(h23, *(__half2*)&g.y);
            if (n == 0) { m01 = v01; m23 = v23; }
            else        { m01 = __hmax2(m01, v01); m23 = __hmax2(m23, v23); }
        }
        float2 f01 = __half22float2(m01);
        float2 f23 = __half22float2(m23);
        acc0 += f01.x; acc1 += f01.y;
        acc2 += f23.x; acc3 += f23.y;
    }
    ((float4*)&out[((size_t)d*2048 + p)*12])[rg] = make_float4(acc0, acc1, acc2, acc3);
}

// ---------------- launch ----------------------------------------------------
extern "C" void kernel_launch(void* const* d_in, const int* in_sizes, int n_in,
                              void* d_out, int out_size) {
    const int*   nbr   = (const int*)d_in[0];
    const float* verts = (const float*)d_in[1];
    const float* fmap  = (const float*)d_in[2];
    const float* W     = (const float*)d_in[3];
    const float* bias  = (const float*)d_in[4];
    const float* dirs  = (const float*)d_in[5];
    const float* fcw   = (const float*)d_in[6];
    float* out    = (float*)d_out;              // (1,32,2048,12)
    float* fm_out = out + 32*2048*12;           // (1,32,2048,3)

    k_fmprep<<<328, 256>>>(fmap, fcw, W, bias, dirs, fm_out);
    k_ka<<<dim3(13, 64), 256>>>();
    k_final<<<512, 384>>>(nbr, verts, out);
}

// round 11
// speedup vs baseline: 1.0325x; 1.0325x over previous
#include <cuda_runtime.h>
#include <cuda_fp16.h>
#include <math.h>
#include <float.h>

// B=1, C_IN=32, D_OUT=32, P=2048, N=10, A=12
typedef unsigned long long ull;

// ---------------- packed f32x2 helpers (sm_103a) ---------------------------
__device__ __forceinline__ ull f2pk(float lo, float hi) {
    ull r; asm("mov.b64 %0,{%1,%2};" : "=l"(r) : "f"(lo), "f"(hi)); return r;
}
__device__ __forceinline__ void f2up(ull v, float& lo, float& hi) {
    asm("mov.b64 {%0,%1},%2;" : "=f"(lo), "=f"(hi) : "l"(v));
}
__device__ __forceinline__ ull ffma2(ull a, ull b, ull c) {
    ull d; asm("fma.rn.f32x2 %0,%1,%2,%3;" : "=l"(d) : "l"(a), "l"(b), "l"(c)); return d;
}

// ---------------- device scratch ------------------------------------------
__device__ float g_ICO[108];                   // VER[r][i][j] floats (for k_ka)
__device__ float g_KDNT[12 * 3 * 32 * 12];     // [k][i][d][r]
__device__ float g_W2[416 * 96];               // [dk][c*3+j]
__device__ float g_BIASF[416];                 // [dk]
__device__ float g_FMP[1024 * 192];            // [pair][c*3+i][2]  (pair = p>>1)
__device__ __half g_KAH2[2048 * 12 * 32 * 12]; // [q][k][d][r]  fp16, 18.9MB
__device__ float g_CEN[32 * 2048 * 12];        // [d][p][r] center (k==12), fp32

// ---------------- icosa constants: FP64, sqrt-only (no trig) ---------------
__device__ __forceinline__ void icosa_vertex(int r, double* u) {
    const double phi = (1.0 + sqrt(5.0)) * 0.5;
    int ia = r / 6, ib = (r / 3) % 2, t = r % 3;
    double a = ia ? -1.0 : 1.0;
    double b = ib ? -phi : phi;
    double v0, v1, v2;
    if (t == 0)      { v0 = 0.0; v1 = a;   v2 = b; }
    else if (t == 1) { v0 = a;   v1 = b;   v2 = 0.0; }
    else             { v0 = b;   v1 = 0.0; v2 = a; }
    double inv = 1.0 / sqrt(v0*v0 + v1*v1 + v2*v2);
    u[0] = v0*inv; u[1] = v1*inv; u[2] = v2*inv;
}
__device__ __forceinline__ double cos5(int m) {
    const double c1 = 0.30901699437494745;   // cos 72
    const double c2 = -0.8090169943749475;   // cos 144
    return (m == 0) ? 1.0 : (m == 1 || m == 4) ? c1 : c2;
}
__device__ __forceinline__ double sin5(int m) {
    const double s1 = 0.9510565162951535;    // sin 72
    const double s2 = 0.5877852522924731;    // sin 144
    return (m == 0) ? 0.0 : (m == 1) ? s1 : (m == 2) ? s2 : (m == 3) ? -s2 : -s1;
}
__device__ __forceinline__ float ver_elem(int tid) {
    int r = tid / 9, e = tid % 9, i = e / 3, j = e % 3;
    double u[3]; icosa_vertex(r, u);
    double c = u[2];
    double axx = -u[1], axy = u[0];
    double s = sqrt(axx*axx + axy*axy);
    double R[3][3];
    if (s < 1e-9) {
        for (int a = 0; a < 3; a++) for (int b = 0; b < 3; b++) R[a][b] = 0.0;
        R[0][0] = 1.0; R[1][1] = (c > 0) ? 1.0 : -1.0; R[2][2] = (c > 0) ? 1.0 : -1.0;
    } else {
        double kx = axx / s, ky = axy / s;
        double K[3][3] = {{0, 0, ky}, {0, 0, -kx}, {-ky, kx, 0}};
        double KK[3][3];
        for (int a = 0; a < 3; a++)
            for (int b = 0; b < 3; b++) {
                double acc = 0.0;
                for (int q = 0; q < 3; q++) acc += K[a][q]*K[q][b];
                KK[a][b] = acc;
            }
        for (int a = 0; a < 3; a++)
            for (int b = 0; b < 3; b++)
                R[a][b] = (a == b ? 1.0 : 0.0) + s*K[a][b] + (1.0 - c)*KK[a][b];
    }
    return (float)R[i][j];
}

// ---------------- kernel 1: fused fm (blocks 0-255) + weight prep (256-327)
__global__ void __launch_bounds__(256) k_fmprep(const float* __restrict__ fmap,
                                                const float* __restrict__ fcw,
                                                const float* __restrict__ W,
                                                const float* __restrict__ bias,
                                                const float* __restrict__ dirs,
                                                float* __restrict__ fm_out) {
    int tid = threadIdx.x;
    if (blockIdx.x < 256) {
        // ---- fm path: 8 warps x 1 point each ----
        __shared__ float FCT[32*33];
        __shared__ float Xs[8][384];
        __shared__ float VSs[36];
        int w = tid >> 5, lane = tid & 31;
        int p = blockIdx.x*8 + w;
        // issue the long-latency fmap loads FIRST (cold DRAM)
        const float4* src = (const float4*)&fmap[((size_t)lane*2048 + p)*12];
        float4 x0 = src[0], x1 = src[1], x2 = src[2];
        // then stage the small L2-resident tables
        for (int i = tid; i < 1024; i += 256) {
            int r = i >> 5, cc = i & 31;
            FCT[cc*33 + r] = fcw[i];
        }
        if (tid < 12) {
            double u[3]; icosa_vertex(tid, u);
            VSs[tid*3+0] = (float)u[0];
            VSs[tid*3+1] = (float)u[1];
            VSs[tid*3+2] = (float)u[2];
        }
        Xs[w][0*32+lane] = x0.x;  Xs[w][1*32+lane]  = x0.y;
        Xs[w][2*32+lane] = x0.z;  Xs[w][3*32+lane]  = x0.w;
        Xs[w][4*32+lane] = x1.x;  Xs[w][5*32+lane]  = x1.y;
        Xs[w][6*32+lane] = x1.z;  Xs[w][7*32+lane]  = x1.w;
        Xs[w][8*32+lane] = x2.x;  Xs[w][9*32+lane]  = x2.y;
        Xs[w][10*32+lane] = x2.z; Xs[w][11*32+lane] = x2.w;
        __syncthreads();

        float L[12];
#pragma unroll
        for (int a = 0; a < 12; a++) L[a] = 0.f;
#pragma unroll
        for (int cc = 0; cc < 32; cc++) {
            float fc = FCT[cc*33 + lane];
#pragma unroll
            for (int a = 0; a < 12; a++) L[a] += Xs[w][a*32+cc] * fc;
        }
        float mx = L[0];
#pragma unroll
        for (int a = 1; a < 12; a++) mx = fmaxf(mx, L[a]);
        float e[12], s = 0.f;
#pragma unroll
        for (int a = 0; a < 12; a++) { e[a] = expf(L[a] - mx); s += e[a]; }
        float inv = 1.f / s;
        float f0 = 0.f, f1 = 0.f, f2 = 0.f;
#pragma unroll
        for (int a = 0; a < 12; a++) {
            float y = e[a] * inv * Xs[w][a*32+lane];
            f0 += y * VSs[a*3+0];
            f1 += y * VSs[a*3+1];
            f2 += y * VSs[a*3+2];
        }
        float* fp = &g_FMP[((size_t)(p >> 1)*96 + lane*3)*2 + (p & 1)];
        fp[0] = f0; fp[2] = f1; fp[4] = f2;
        fm_out[((size_t)lane*2048 + p)*3 + 0] = f0;
        fm_out[((size_t)lane*2048 + p)*3 + 1] = f1;
        fm_out[((size_t)lane*2048 + p)*3 + 2] = f2;
    } else {
        // ---- weight prep path ----
        __shared__ float SYMR[45];
        __shared__ float VER[108];
        int t = (blockIdx.x - 256) * 256 + tid;
        // prefetch the global operands this thread will need (overlap w/ FP64)
        float pre[3]; pre[0] = pre[1] = pre[2] = 0.f;
        float preBias = 0.f;
        if (t < 4608) {
            int d = t / 144, k = (t / 12) % 12;
            if (k >= 2) {
                int kk = (k - 2) / 5;
                pre[0] = dirs[d*6 + kk*3 + 0];
                pre[1] = dirs[d*6 + kk*3 + 1];
                pre[2] = dirs[d*6 + kk*3 + 2];
            }
        } else if (t < 4608 + 13312) {
            int id = t - 4608;
            int dk = id / 32, c = id % 32;
            int d = dk / 13, k = dk % 13;
            const float* wr = W + (d*32 + c)*9;
            if (k == 0)       pre[0] = wr[0];
            else if (k == 1)  pre[0] = wr[1];
            else if (k == 12) pre[0] = wr[8];
            else {
                int kk = (k - 2) / 5;
                pre[0] = wr[2 + kk*3 + 0];
                pre[1] = wr[2 + kk*3 + 1];
                pre[2] = wr[2 + kk*3 + 2];
            }
        } else if (t < 4608 + 13312 + 416) {
            int dk = t - (4608 + 13312);
            int d = dk / 13, k = dk % 13;
            int col = (k == 0) ? 0 : (k == 1) ? 1 : (k <= 6) ? 2 : (k <= 11) ? 3 : 4;
            preBias = bias[d*5 + col];
        }
        if (tid < 45) {
            int m = tid / 9, e = tid % 9, i = e / 3, j = e % 3;
            double ct = cos5(m), st = sin5(m);
            double R[3][3] = {{ct, -st, 0.0}, {st, ct, 0.0}, {0.0, 0.0, 1.0}};
            SYMR[tid] = (float)R[i][j];
        }
        if (tid < 108) {
            float v = ver_elem(tid);
            VER[tid] = v;
            if (blockIdx.x == 256) g_ICO[tid] = v;   // publish for k_ka
        }
        __syncthreads();
        if (t < 4608) {
            int d = t / 144, k = (t / 12) % 12, r = t % 12;
            float vv[3];
            if (k == 0)      { vv[0] = 0.f; vv[1] = 0.f; vv[2] = 1.f; }
            else if (k == 1) { vv[0] = 0.f; vv[1] = 0.f; vv[2] = -1.f; }
            else {
                int m = (k - 2) % 5;
                float d0 = pre[0], d1 = pre[1], d2 = pre[2];
                float nrm = sqrtf(d0*d0 + d1*d1 + d2*d2);
                float inv = 1.f / fmaxf(nrm, 1e-12f);
                d0 *= inv; d1 *= inv; d2 *= inv;
                for (int i = 0; i < 3; i++)
                    vv[i] = SYMR[m*9+i*3+0]*d0 + SYMR[m*9+i*3+1]*d1 + SYMR[m*9+i*3+2]*d2;
            }
            for (int i = 0; i < 3; i++) {
                float o = VER[r*9+i*3+0]*vv[0] + VER[r*9+i*3+1]*vv[1] + VER[r*9+i*3+2]*vv[2];
                g_KDNT[((k*3 + i)*32 + d)*12 + r] = o;
            }
        } else if (t < 4608 + 13312) {
            int id = t - 4608;
            int dk = id / 32, c = id % 32;
            int k = dk % 13;
            float wf[3];
            if (k == 0)       { wf[0] = 0.f; wf[1] = 0.f; wf[2] = pre[0]; }
            else if (k == 1)  { wf[0] = 0.f; wf[1] = 0.f; wf[2] = -pre[0]; }
            else if (k == 12) { wf[0] = 0.f; wf[1] = 0.f; wf[2] = pre[0]; }
            else {
                int m = (k - 2) % 5;
                for (int i = 0; i < 3; i++)
                    wf[i] = SYMR[m*9+i*3+0]*pre[0] + SYMR[m*9+i*3+1]*pre[1] + SYMR[m*9+i*3+2]*pre[2];
            }
            g_W2[dk*96 + c*3 + 0] = wf[0];
            g_W2[dk*96 + c*3 + 1] = wf[1];
            g_W2[dk*96 + c*3 + 2] = wf[2];
        } else if (t < 4608 + 13312 + 416) {
            int dk = t - (4608 + 13312);
            g_BIASF[dk] = preBias;
        }
    }
}

// ---------------- kernel 2: ka — one k x 32 d x 32 p per block -------------
// 256 thr = 32 d x 8 ps; NO min-blocks clause (avoid register spills)
__global__ void __launch_bounds__(256) k_ka() {
    __shared__ float  Ws[32*97];    // [d][c*3+j]
    __shared__ ull    Fp[16][98];   // [pair][c*3+i] = {fm[even], fm[odd]}
    __shared__ float2 verd[108];
    __shared__ float2 biasd[32];
    __shared__ __half Hs[32*384];   // [pl][d*12+r]  768B per point row
    int k  = blockIdx.x;            // 0..12
    int p0 = blockIdx.y * 32;
    int tid = threadIdx.x;

    for (int i = tid; i < 32*96; i += 256) {
        int dd = i / 96, q = i % 96;
        Ws[dd*97 + q] = g_W2[(dd*13 + k)*96 + q];
    }
    {
        const float4* src = (const float4*)&g_FMP[(size_t)(p0 >> 1) * 192];
        for (int i = tid; i < 16*48; i += 256)
            ((float4*)&Fp[i / 48][0])[i % 48] = src[i];
    }
    if (tid < 108) { float v = g_ICO[tid]; verd[tid] = make_float2(v, v); }
    if (tid < 32)  { float bv = g_BIASF[tid*13 + k]; biasd[tid] = make_float2(bv, bv); }
    __syncthreads();

    int d  = tid & 31;
    int ps = tid >> 5;              // 0..7: pairs 2ps, 2ps+1 = points p0+4ps..+3
    const float* wrow = &Ws[d*97];
    const ull* fA = Fp[2*ps];
    const ull* fB = Fp[2*ps + 1];

    ull GA[9], GB[9];
#pragma unroll
    for (int q = 0; q < 9; q++) { GA[q] = 0ULL; GB[q] = 0ULL; }

#pragma unroll 4
    for (int cp = 0; cp < 16; cp++) {   // c = 2cp, 2cp+1
        float we0 = wrow[6*cp+0], we1 = wrow[6*cp+1], we2 = wrow[6*cp+2];
        float wo0 = wrow[6*cp+3], wo1 = wrow[6*cp+4], wo2 = wrow[6*cp+5];
        ull We0 = f2pk(we0, we0), We1 = f2pk(we1, we1), We2 = f2pk(we2, we2);
        ull Wo0 = f2pk(wo0, wo0), Wo1 = f2pk(wo1, wo1), Wo2 = f2pk(wo2, wo2);
        ulonglong2 aA = *(const ulonglong2*)&fA[6*cp];       // f0e, f1e
        ulonglong2 aB = *(const ulonglong2*)&fA[6*cp+2];     // f2e, f0o
        ulonglong2 aC = *(const ulonglong2*)&fA[6*cp+4];     // f1o, f2o
        ulonglong2 bA = *(const ulonglong2*)&fB[6*cp];
        ulonglong2 bB = *(const ulonglong2*)&fB[6*cp+2];
        ulonglong2 bC = *(const ulonglong2*)&fB[6*cp+4];
        // even c
        GA[0] = ffma2(We0, aA.x, GA[0]); GA[1] = ffma2(We0, aA.y, GA[1]); GA[2] = ffma2(We0, aB.x, GA[2]);
        GA[3] = ffma2(We1, aA.x, GA[3]); GA[4] = ffma2(We1, aA.y, GA[4]); GA[5] = ffma2(We1, aB.x, GA[5]);
        GA[6] = ffma2(We2, aA.x, GA[6]); GA[7] = ffma2(We2, aA.y, GA[7]); GA[8] = ffma2(We2, aB.x, GA[8]);
        GB[0] = ffma2(We0, bA.x, GB[0]); GB[1] = ffma2(We0, bA.y, GB[1]); GB[2] = ffma2(We0, bB.x, GB[2]);
        GB[3] = ffma2(We1, bA.x, GB[3]); GB[4] = ffma2(We1, bA.y, GB[4]); GB[5] = ffma2(We1, bB.x, GB[5]);
        GB[6] = ffma2(We2, bA.x, GB[6]); GB[7] = ffma2(We2, bA.y, GB[7]); GB[8] = ffma2(We2, bB.x, GB[8]);
        // odd c
        GA[0] = ffma2(Wo0, aB.y, GA[0]); GA[1] = ffma2(Wo0, aC.x, GA[1]); GA[2] = ffma2(Wo0, aC.y, GA[2]);
        GA[3] = ffma2(Wo1, aB.y, GA[3]); GA[4] = ffma2(Wo1, aC.x, GA[4]); GA[5] = ffma2(Wo1, aC.y, GA[5]);
        GA[6] = ffma2(Wo2, aB.y, GA[6]); GA[7] = ffma2(Wo2, aC.x, GA[7]); GA[8] = ffma2(Wo2, aC.y, GA[8]);
        GB[0] = ffma2(Wo0, bB.y, GB[0]); GB[1] = ffma2(Wo0, bC.x, GB[1]); GB[2] = ffma2(Wo0, bC.y, GB[2]);
        GB[3] = ffma2(Wo1, bB.y, GB[3]); GB[4] = ffma2(Wo1, bC.x, GB[4]); GB[5] = ffma2(Wo1, bC.y, GB[5]);
        GB[6] = ffma2(Wo2, bB.y, GB[6]); GB[7] = ffma2(Wo2, bC.x, GB[7]); GB[8] = ffma2(Wo2, bC.y, GB[8]);
    }

    ull bias2 = *(const ull*)&biasd[d];
    int pl0 = ps*4;                 // pair A -> points pl0, pl0+1; pair B -> +2,+3

#pragma unroll
    for (int g4 = 0; g4 < 3; g4++) {
        ull oA[4], oB[4];
#pragma unroll
        for (int rr = 0; rr < 4; rr++) {
            int r = g4*4 + rr;
            ull sA = bias2, sB = bias2;
#pragma unroll
            for (int i = 0; i < 3; i++)
#pragma unroll
                for (int j = 0; j < 3; j++) {
                    ull v = *(const ull*)&verd[r*9 + i*3 + j];
                    sA = ffma2(v, GA[j*3 + i], sA);
                    sB = ffma2(v, GB[j*3 + i], sB);
                }
            oA[rr] = sA; oB[rr] = sB;
        }
        float a0l,a0h,a1l,a1h,a2l,a2h,a3l,a3h;
        float b0l,b0h,b1l,b1h,b2l,b2h,b3l,b3h;
        f2up(oA[0], a0l, a0h); f2up(oA[1], a1l, a1h);
        f2up(oA[2], a2l, a2h); f2up(oA[3], a3l, a3h);
        f2up(oB[0], b0l, b0h); f2up(oB[1], b1l, b1h);
        f2up(oB[2], b2l, b2h); f2up(oB[3], b3l, b3h);
        if (k == 12) {
            *(float4*)&g_CEN[((size_t)d*2048 + p0 + pl0 + 0)*12 + g4*4] = make_float4(a0l, a1l, a2l, a3l);
            *(float4*)&g_CEN[((size_t)d*2048 + p0 + pl0 + 1)*12 + g4*4] = make_float4(a0h, a1h, a2h, a3h);
            *(float4*)&g_CEN[((size_t)d*2048 + p0 + pl0 + 2)*12 + g4*4] = make_float4(b0l, b1l, b2l, b3l);
            *(float4*)&g_CEN[((size_t)d*2048 + p0 + pl0 + 3)*12 + g4*4] = make_float4(b0h, b1h, b2h, b3h);
        } else {
            __half2 hA0 = __floats2half2_rn(a0l, a1l), hA1 = __floats2half2_rn(a2l, a3l);
            __half2 hB0 = __floats2half2_rn(a0h, a1h), hB1 = __floats2half2_rn(a2h, a3h);
            __half2 hC0 = __floats2half2_rn(b0l, b1l), hC1 = __floats2half2_rn(b2l, b3l);
            __half2 hD0 = __floats2half2_rn(b0h, b1h), hD1 = __floats2half2_rn(b2h, b3h);
            *(ull*)&Hs[(pl0+0)*384 + d*12 + g4*4] = ((ull)*(unsigned*)&hA1 << 32) | *(unsigned*)&hA0;
            *(ull*)&Hs[(pl0+1)*384 + d*12 + g4*4] = ((ull)*(unsigned*)&hB1 << 32) | *(unsigned*)&hB0;
            *(ull*)&Hs[(pl0+2)*384 + d*12 + g4*4] = ((ull)*(unsigned*)&hC1 << 32) | *(unsigned*)&hC0;
            *(ull*)&Hs[(pl0+3)*384 + d*12 + g4*4] = ((ull)*(unsigned*)&hD1 << 32) | *(unsigned*)&hD0;
        }
    }

    if (k < 12) {
        __syncthreads();
        // dense write-out: 32 rows x 768B, coalesced uint4
        const uint4* hsrc = (const uint4*)Hs;
        uint4* dst = (uint4*)g_KAH2;
        int kbase = k * 48;             // uint4 offset within point row (576/pt)
        for (int i = tid; i < 1536; i += 256) {
            int pl = i / 48, off = i % 48;
            dst[(size_t)(p0 + pl)*576 + kbase + off] = hsrc[pl*48 + off];
        }
    }
}

// ---------------- kernel 3: theta + gather + max_n + sum_k + center -------
// block = 4 points x 96 (d,rg); scalar fp32 theta, half2 gather math (R9)
__global__ void __launch_bounds__(384, 2) k_final(const int* __restrict__ nbr,
                                                  const float* __restrict__ verts,
                                                  float* __restrict__ out) {
    __shared__ float nds[4][32];
    __shared__ int qoffs[4][10];
    int tid = threadIdx.x;
    if (tid < 40) {
        int pp2 = tid / 10, n = tid % 10;
        int p2 = blockIdx.x*4 + pp2;
        int q = nbr[p2*10 + n];
        qoffs[pp2][n] = q * 9216;
        float dx = verts[q*3+0] - verts[p2*3+0];
        float dy = verts[q*3+1] - verts[p2*3+1];
        float dz = verts[q*3+2] - verts[p2*3+2];
        float nrm = sqrtf(dx*dx + dy*dy + dz*dz);
        float inv = 1.f / fmaxf(nrm, 1e-12f);
        nds[pp2][n*3+0] = dx*inv;
        nds[pp2][n*3+1] = dy*inv;
        nds[pp2][n*3+2] = dz*inv;
    }
    __syncthreads();
    int pp = tid / 96;
    int u  = tid % 96;
    int d  = u / 3, rg = u % 3;
    int p  = blockIdx.x*4 + pp;

    int qb[10];
#pragma unroll
    for (int n = 0; n < 10; n++) qb[n] = qoffs[pp][n];
    const float* ndp = nds[pp];

    float4 a4 = ((const float4*)&g_CEN[((size_t)d*2048 + p)*12])[rg];
    float acc0 = a4.x, acc1 = a4.y, acc2 = a4.z, acc3 = a4.w;

    const char* base = ((const char*)g_KAH2) + (size_t)d*24 + rg*8;
    const __half2 zero2 = __half2half2(__ushort_as_half(0));

#pragma unroll 1
    for (int k = 0; k < 12; k++) {
        const float* ktb = &g_KDNT[k*1152 + d*12 + rg*4];
        float4 c0 = __ldg((const float4*)(ktb + 0));
        float4 c1 = __ldg((const float4*)(ktb + 384));
        float4 c2 = __ldg((const float4*)(ktb + 768));
        const char* kbase = base + k*768;

        __half2 m01, m23;
#pragma unroll
        for (int n = 0; n < 10; n++) {
            float nx = ndp[n*3+0], ny = ndp[n*3+1], nz = ndp[n*3+2];
            float t0 = fmaf(c0.x, nx, fmaf(c1.x, ny, c2.x*nz));
            float t1 = fmaf(c0.y, nx, fmaf(c1.y, ny, c2.y*nz));
            float t2 = fmaf(c0.z, nx, fmaf(c1.z, ny, c2.z*nz));
            float t3 = fmaf(c0.w, nx, fmaf(c1.w, ny, c2.w*nz));
            __half2 h01 = __hmax2(__floats2half2_rn(t0, t1), zero2);
            __half2 h23 = __hmax2(__floats2half2_rn(t2, t3), zero2);
            uint2 g = *(const uint2*)(kbase + qb[n]);
            __half2 v01 = __hmul2(h01, *(__half2*)&g.x);
            __half2 v23 = __hmul2(h23, *(__half2*)&g.y);
            if (n == 0) { m01 = v01; m23 = v23; }
            else        { m01 = __hmax2(m01, v01); m23 = __hmax2(m23, v23); }
        }
        float2 f01 = __half22float2(m01);
        float2 f23 = __half22float2(m23);
        acc0 += f01.x; acc1 += f01.y;
        acc2 += f23.x; acc3 += f23.y;
    }
    ((float4*)&out[((size_t)d*2048 + p)*12])[rg] = make_float4(acc0, acc1, acc2, acc3);
}

// ---------------- launch ----------------------------------------------------
extern "C" void kernel_launch(void* const* d_in, const int* in_sizes, int n_in,
                              void* d_out, int out_size) {
    const int*   nbr   = (const int*)d_in[0];
    const float* verts = (const float*)d_in[1];
    const float* fmap  = (const float*)d_in[2];
    const float* W     = (const float*)d_in[3];
    const float* bias  = (const float*)d_in[4];
    const float* dirs  = (const float*)d_in[5];
    const float* fcw   = (const float*)d_in[6];
    float* out    = (float*)d_out;              // (1,32,2048,12)
    float* fm_out = out + 32*2048*12;           // (1,32,2048,3)

    k_fmprep<<<328, 256>>>(fmap, fcw, W, bias, dirs, fm_out);
    k_ka<<<dim3(13, 64), 256>>>();
    k_final<<<512, 384>>>(nbr, verts, out);
}

// round 12
// speedup vs baseline: 1.0335x; 1.0010x over previous
#include <cuda_runtime.h>
#include <cuda_fp16.h>
#include <math.h>
#include <float.h>

// B=1, C_IN=32, D_OUT=32, P=2048, N=10, A=12
typedef unsigned long long ull;

// ---------------- packed f32x2 helpers (sm_103a) ---------------------------
__device__ __forceinline__ ull f2pk(float lo, float hi) {
    ull r; asm("mov.b64 %0,{%1,%2};" : "=l"(r) : "f"(lo), "f"(hi)); return r;
}
__device__ __forceinline__ void f2up(ull v, float& lo, float& hi) {
    asm("mov.b64 {%0,%1},%2;" : "=f"(lo), "=f"(hi) : "l"(v));
}
__device__ __forceinline__ ull ffma2(ull a, ull b, ull c) {
    ull d; asm("fma.rn.f32x2 %0,%1,%2,%3;" : "=l"(d) : "l"(a), "l"(b), "l"(c)); return d;
}

// ---------------- device scratch ------------------------------------------
__device__ float g_ICO[108];                   // VER[r][i][j] floats (for k_ka)
__device__ float g_KDNT[12 * 3 * 32 * 12];     // [k][i][d][r]
__device__ float g_W2[416 * 96];               // [dk][c*3+j]
__device__ float g_BIASF[416];                 // [dk]
__device__ float g_FMP[1024 * 192];            // [pair][c*3+i][2]  (pair = p>>1)
__device__ __half g_KAH2[2048 * 12 * 32 * 12]; // [q][k][d][r]  fp16, 18.9MB
__device__ float g_CEN[32 * 2048 * 12];        // [d][p][r] center (k==12), fp32

// ---------------- icosa constants: FP64, sqrt-only (no trig) ---------------
__device__ __forceinline__ void icosa_vertex(int r, double* u) {
    const double phi = (1.0 + sqrt(5.0)) * 0.5;
    int ia = r / 6, ib = (r / 3) % 2, t = r % 3;
    double a = ia ? -1.0 : 1.0;
    double b = ib ? -phi : phi;
    double v0, v1, v2;
    if (t == 0)      { v0 = 0.0; v1 = a;   v2 = b; }
    else if (t == 1) { v0 = a;   v1 = b;   v2 = 0.0; }
    else             { v0 = b;   v1 = 0.0; v2 = a; }
    double inv = 1.0 / sqrt(v0*v0 + v1*v1 + v2*v2);
    u[0] = v0*inv; u[1] = v1*inv; u[2] = v2*inv;
}
__device__ __forceinline__ double cos5(int m) {
    const double c1 = 0.30901699437494745;   // cos 72
    const double c2 = -0.8090169943749475;   // cos 144
    return (m == 0) ? 1.0 : (m == 1 || m == 4) ? c1 : c2;
}
__device__ __forceinline__ double sin5(int m) {
    const double s1 = 0.9510565162951535;    // sin 72
    const double s2 = 0.5877852522924731;    // sin 144
    return (m == 0) ? 0.0 : (m == 1) ? s1 : (m == 2) ? s2 : (m == 3) ? -s2 : -s1;
}
__device__ __forceinline__ float ver_elem(int tid) {
    int r = tid / 9, e = tid % 9, i = e / 3, j = e % 3;
    double u[3]; icosa_vertex(r, u);
    double c = u[2];
    double axx = -u[1], axy = u[0];
    double s = sqrt(axx*axx + axy*axy);
    double R[3][3];
    if (s < 1e-9) {
        for (int a = 0; a < 3; a++) for (int b = 0; b < 3; b++) R[a][b] = 0.0;
        R[0][0] = 1.0; R[1][1] = (c > 0) ? 1.0 : -1.0; R[2][2] = (c > 0) ? 1.0 : -1.0;
    } else {
        double kx = axx / s, ky = axy / s;
        double K[3][3] = {{0, 0, ky}, {0, 0, -kx}, {-ky, kx, 0}};
        double KK[3][3];
        for (int a = 0; a < 3; a++)
            for (int b = 0; b < 3; b++) {
                double acc = 0.0;
                for (int q = 0; q < 3; q++) acc += K[a][q]*K[q][b];
                KK[a][b] = acc;
            }
        for (int a = 0; a < 3; a++)
            for (int b = 0; b < 3; b++)
                R[a][b] = (a == b ? 1.0 : 0.0) + s*K[a][b] + (1.0 - c)*KK[a][b];
    }
    return (float)R[i][j];
}

// ---------------- kernel 1: fused fm (blocks 0-255) + weight prep (256-327)
__global__ void __launch_bounds__(256) k_fmprep(const float* __restrict__ fmap,
                                                const float* __restrict__ fcw,
                                                const float* __restrict__ W,
                                                const float* __restrict__ bias,
                                                const float* __restrict__ dirs,
                                                float* __restrict__ fm_out) {
    int tid = threadIdx.x;
    if (blockIdx.x < 256) {
        // ---- fm path: 8 warps x 1 point each ----
        __shared__ float FCT[32*33];
        __shared__ float Xs[8][384];
        __shared__ float VSs[36];
        int w = tid >> 5, lane = tid & 31;
        int p = blockIdx.x*8 + w;
        const float4* src = (const float4*)&fmap[((size_t)lane*2048 + p)*12];
        float4 x0 = src[0], x1 = src[1], x2 = src[2];
        for (int i = tid; i < 1024; i += 256) {
            int r = i >> 5, cc = i & 31;
            FCT[cc*33 + r] = fcw[i];
        }
        if (tid < 12) {
            double u[3]; icosa_vertex(tid, u);
            VSs[tid*3+0] = (float)u[0];
            VSs[tid*3+1] = (float)u[1];
            VSs[tid*3+2] = (float)u[2];
        }
        Xs[w][0*32+lane] = x0.x;  Xs[w][1*32+lane]  = x0.y;
        Xs[w][2*32+lane] = x0.z;  Xs[w][3*32+lane]  = x0.w;
        Xs[w][4*32+lane] = x1.x;  Xs[w][5*32+lane]  = x1.y;
        Xs[w][6*32+lane] = x1.z;  Xs[w][7*32+lane]  = x1.w;
        Xs[w][8*32+lane] = x2.x;  Xs[w][9*32+lane]  = x2.y;
        Xs[w][10*32+lane] = x2.z; Xs[w][11*32+lane] = x2.w;
        __syncthreads();

        float L[12];
#pragma unroll
        for (int a = 0; a < 12; a++) L[a] = 0.f;
#pragma unroll
        for (int cc = 0; cc < 32; cc++) {
            float fc = FCT[cc*33 + lane];
#pragma unroll
            for (int a = 0; a < 12; a++) L[a] += Xs[w][a*32+cc] * fc;
        }
        float mx = L[0];
#pragma unroll
        for (int a = 1; a < 12; a++) mx = fmaxf(mx, L[a]);
        float e[12], s = 0.f;
#pragma unroll
        for (int a = 0; a < 12; a++) { e[a] = expf(L[a] - mx); s += e[a]; }
        float inv = 1.f / s;
        float f0 = 0.f, f1 = 0.f, f2 = 0.f;
#pragma unroll
        for (int a = 0; a < 12; a++) {
            float y = e[a] * inv * Xs[w][a*32+lane];
            f0 += y * VSs[a*3+0];
            f1 += y * VSs[a*3+1];
            f2 += y * VSs[a*3+2];
        }
        float* fp = &g_FMP[((size_t)(p >> 1)*96 + lane*3)*2 + (p & 1)];
        fp[0] = f0; fp[2] = f1; fp[4] = f2;
        fm_out[((size_t)lane*2048 + p)*3 + 0] = f0;
        fm_out[((size_t)lane*2048 + p)*3 + 1] = f1;
        fm_out[((size_t)lane*2048 + p)*3 + 2] = f2;
    } else {
        // ---- weight prep path ----
        __shared__ float SYMR[45];
        __shared__ float VER[108];
        int t = (blockIdx.x - 256) * 256 + tid;
        float pre[3]; pre[0] = pre[1] = pre[2] = 0.f;
        float preBias = 0.f;
        if (t < 4608) {
            int d = t / 144, k = (t / 12) % 12;
            if (k >= 2) {
                int kk = (k - 2) / 5;
                pre[0] = dirs[d*6 + kk*3 + 0];
                pre[1] = dirs[d*6 + kk*3 + 1];
                pre[2] = dirs[d*6 + kk*3 + 2];
            }
        } else if (t < 4608 + 13312) {
            int id = t - 4608;
            int dk = id / 32, c = id % 32;
            int d = dk / 13, k = dk % 13;
            const float* wr = W + (d*32 + c)*9;
            if (k == 0)       pre[0] = wr[0];
            else if (k == 1)  pre[0] = wr[1];
            else if (k == 12) pre[0] = wr[8];
            else {
                int kk = (k - 2) / 5;
                pre[0] = wr[2 + kk*3 + 0];
                pre[1] = wr[2 + kk*3 + 1];
                pre[2] = wr[2 + kk*3 + 2];
            }
        } else if (t < 4608 + 13312 + 416) {
            int dk = t - (4608 + 13312);
            int d = dk / 13, k = dk % 13;
            int col = (k == 0) ? 0 : (k == 1) ? 1 : (k <= 6) ? 2 : (k <= 11) ? 3 : 4;
            preBias = bias[d*5 + col];
        }
        if (tid < 45) {
            int m = tid / 9, e = tid % 9, i = e / 3, j = e % 3;
            double ct = cos5(m), st = sin5(m);
            double R[3][3] = {{ct, -st, 0.0}, {st, ct, 0.0}, {0.0, 0.0, 1.0}};
            SYMR[tid] = (float)R[i][j];
        }
        if (tid < 108) {
            float v = ver_elem(tid);
            VER[tid] = v;
            if (blockIdx.x == 256) g_ICO[tid] = v;   // publish for k_ka
        }
        __syncthreads();
        if (t < 4608) {
            int d = t / 144, k = (t / 12) % 12, r = t % 12;
            float vv[3];
            if (k == 0)      { vv[0] = 0.f; vv[1] = 0.f; vv[2] = 1.f; }
            else if (k == 1) { vv[0] = 0.f; vv[1] = 0.f; vv[2] = -1.f; }
            else {
                int m = (k - 2) % 5;
                float d0 = pre[0], d1 = pre[1], d2 = pre[2];
                float nrm = sqrtf(d0*d0 + d1*d1 + d2*d2);
                float inv = 1.f / fmaxf(nrm, 1e-12f);
                d0 *= inv; d1 *= inv; d2 *= inv;
                for (int i = 0; i < 3; i++)
                    vv[i] = SYMR[m*9+i*3+0]*d0 + SYMR[m*9+i*3+1]*d1 + SYMR[m*9+i*3+2]*d2;
            }
            for (int i = 0; i < 3; i++) {
                float o = VER[r*9+i*3+0]*vv[0] + VER[r*9+i*3+1]*vv[1] + VER[r*9+i*3+2]*vv[2];
                g_KDNT[((k*3 + i)*32 + d)*12 + r] = o;
            }
        } else if (t < 4608 + 13312) {
            int id = t - 4608;
            int dk = id / 32, c = id % 32;
            int k = dk % 13;
            float wf[3];
            if (k == 0)       { wf[0] = 0.f; wf[1] = 0.f; wf[2] = pre[0]; }
            else if (k == 1)  { wf[0] = 0.f; wf[1] = 0.f; wf[2] = -pre[0]; }
            else if (k == 12) { wf[0] = 0.f; wf[1] = 0.f; wf[2] = pre[0]; }
            else {
                int m = (k - 2) % 5;
                for (int i = 0; i < 3; i++)
                    wf[i] = SYMR[m*9+i*3+0]*pre[0] + SYMR[m*9+i*3+1]*pre[1] + SYMR[m*9+i*3+2]*pre[2];
            }
            g_W2[dk*96 + c*3 + 0] = wf[0];
            g_W2[dk*96 + c*3 + 1] = wf[1];
            g_W2[dk*96 + c*3 + 2] = wf[2];
        } else if (t < 4608 + 13312 + 416) {
            int dk = t - (4608 + 13312);
            g_BIASF[dk] = preBias;
        }
    }
}

// ---------------- kernel 2: ka — one k x 32 d x 32 p per block -------------
// 256 thr = 32 d x 8 ps; NO min-blocks clause (avoid register spills)
__global__ void __launch_bounds__(256) k_ka() {
    __shared__ float  Ws[32*97];    // [d][c*3+j]
    __shared__ ull    Fp[16][98];   // [pair][c*3+i] = {fm[even], fm[odd]}
    __shared__ float2 verd[108];
    __shared__ float2 biasd[32];
    __shared__ __half Hs[32*384];   // [pl][d*12+r]  768B per point row
    int k  = blockIdx.x;            // 0..12
    int p0 = blockIdx.y * 32;
    int tid = threadIdx.x;

    for (int i = tid; i < 32*96; i += 256) {
        int dd = i / 96, q = i % 96;
        Ws[dd*97 + q] = g_W2[(dd*13 + k)*96 + q];
    }
    {
        const float4* src = (const float4*)&g_FMP[(size_t)(p0 >> 1) * 192];
        for (int i = tid; i < 16*48; i += 256)
            ((float4*)&Fp[i / 48][0])[i % 48] = src[i];
    }
    if (tid < 108) { float v = g_ICO[tid]; verd[tid] = make_float2(v, v); }
    if (tid < 32)  { float bv = g_BIASF[tid*13 + k]; biasd[tid] = make_float2(bv, bv); }
    __syncthreads();

    int d  = tid & 31;
    int ps = tid >> 5;              // 0..7: pairs 2ps, 2ps+1 = points p0+4ps..+3
    const float* wrow = &Ws[d*97];
    const ull* fA = Fp[2*ps];
    const ull* fB = Fp[2*ps + 1];

    ull GA[9], GB[9];
#pragma unroll
    for (int q = 0; q < 9; q++) { GA[q] = 0ULL; GB[q] = 0ULL; }

#pragma unroll 4
    for (int cp = 0; cp < 16; cp++) {   // c = 2cp, 2cp+1
        float we0 = wrow[6*cp+0], we1 = wrow[6*cp+1], we2 = wrow[6*cp+2];
        float wo0 = wrow[6*cp+3], wo1 = wrow[6*cp+4], wo2 = wrow[6*cp+5];
        ull We0 = f2pk(we0, we0), We1 = f2pk(we1, we1), We2 = f2pk(we2, we2);
        ull Wo0 = f2pk(wo0, wo0), Wo1 = f2pk(wo1, wo1), Wo2 = f2pk(wo2, wo2);
        ulonglong2 aA = *(const ulonglong2*)&fA[6*cp];       // f0e, f1e
        ulonglong2 aB = *(const ulonglong2*)&fA[6*cp+2];     // f2e, f0o
        ulonglong2 aC = *(const ulonglong2*)&fA[6*cp+4];     // f1o, f2o
        ulonglong2 bA = *(const ulonglong2*)&fB[6*cp];
        ulonglong2 bB = *(const ulonglong2*)&fB[6*cp+2];
        ulonglong2 bC = *(const ulonglong2*)&fB[6*cp+4];
        // even c
        GA[0] = ffma2(We0, aA.x, GA[0]); GA[1] = ffma2(We0, aA.y, GA[1]); GA[2] = ffma2(We0, aB.x, GA[2]);
        GA[3] = ffma2(We1, aA.x, GA[3]); GA[4] = ffma2(We1, aA.y, GA[4]); GA[5] = ffma2(We1, aB.x, GA[5]);
        GA[6] = ffma2(We2, aA.x, GA[6]); GA[7] = ffma2(We2, aA.y, GA[7]); GA[8] = ffma2(We2, aB.x, GA[8]);
        GB[0] = ffma2(We0, bA.x, GB[0]); GB[1] = ffma2(We0, bA.y, GB[1]); GB[2] = ffma2(We0, bB.x, GB[2]);
        GB[3] = ffma2(We1, bA.x, GB[3]); GB[4] = ffma2(We1, bA.y, GB[4]); GB[5] = ffma2(We1, bB.x, GB[5]);
        GB[6] = ffma2(We2, bA.x, GB[6]); GB[7] = ffma2(We2, bA.y, GB[7]); GB[8] = ffma2(We2, bB.x, GB[8]);
        // odd c
        GA[0] = ffma2(Wo0, aB.y, GA[0]); GA[1] = ffma2(Wo0, aC.x, GA[1]); GA[2] = ffma2(Wo0, aC.y, GA[2]);
        GA[3] = ffma2(Wo1, aB.y, GA[3]); GA[4] = ffma2(Wo1, aC.x, GA[4]); GA[5] = ffma2(Wo1, aC.y, GA[5]);
        GA[6] = ffma2(Wo2, aB.y, GA[6]); GA[7] = ffma2(Wo2, aC.x, GA[7]); GA[8] = ffma2(Wo2, aC.y, GA[8]);
        GB[0] = ffma2(Wo0, bB.y, GB[0]); GB[1] = ffma2(Wo0, bC.x, GB[1]); GB[2] = ffma2(Wo0, bC.y, GB[2]);
        GB[3] = ffma2(Wo1, bB.y, GB[3]); GB[4] = ffma2(Wo1, bC.x, GB[4]); GB[5] = ffma2(Wo1, bC.y, GB[5]);
        GB[6] = ffma2(Wo2, bB.y, GB[6]); GB[7] = ffma2(Wo2, bC.x, GB[7]); GB[8] = ffma2(Wo2, bC.y, GB[8]);
    }

    ull bias2 = *(const ull*)&biasd[d];
    int pl0 = ps*4;                 // pair A -> points pl0, pl0+1; pair B -> +2,+3

#pragma unroll
    for (int g4 = 0; g4 < 3; g4++) {
        ull oA[4], oB[4];
#pragma unroll
        for (int rr = 0; rr < 4; rr++) {
            int r = g4*4 + rr;
            ull sA = bias2, sB = bias2;
#pragma unroll
            for (int i = 0; i < 3; i++)
#pragma unroll
                for (int j = 0; j < 3; j++) {
                    ull v = *(const ull*)&verd[r*9 + i*3 + j];
                    sA = ffma2(v, GA[j*3 + i], sA);
                    sB = ffma2(v, GB[j*3 + i], sB);
                }
            oA[rr] = sA; oB[rr] = sB;
        }
        float a0l,a0h,a1l,a1h,a2l,a2h,a3l,a3h;
        float b0l,b0h,b1l,b1h,b2l,b2h,b3l,b3h;
        f2up(oA[0], a0l, a0h); f2up(oA[1], a1l, a1h);
        f2up(oA[2], a2l, a2h); f2up(oA[3], a3l, a3h);
        f2up(oB[0], b0l, b0h); f2up(oB[1], b1l, b1h);
        f2up(oB[2], b2l, b2h); f2up(oB[3], b3l, b3h);
        if (k == 12) {
            *(float4*)&g_CEN[((size_t)d*2048 + p0 + pl0 + 0)*12 + g4*4] = make_float4(a0l, a1l, a2l, a3l);
            *(float4*)&g_CEN[((size_t)d*2048 + p0 + pl0 + 1)*12 + g4*4] = make_float4(a0h, a1h, a2h, a3h);
            *(float4*)&g_CEN[((size_t)d*2048 + p0 + pl0 + 2)*12 + g4*4] = make_float4(b0l, b1l, b2l, b3l);
            *(float4*)&g_CEN[((size_t)d*2048 + p0 + pl0 + 3)*12 + g4*4] = make_float4(b0h, b1h, b2h, b3h);
        } else {
            __half2 hA0 = __floats2half2_rn(a0l, a1l), hA1 = __floats2half2_rn(a2l, a3l);
            __half2 hB0 = __floats2half2_rn(a0h, a1h), hB1 = __floats2half2_rn(a2h, a3h);
            __half2 hC0 = __floats2half2_rn(b0l, b1l), hC1 = __floats2half2_rn(b2l, b3l);
            __half2 hD0 = __floats2half2_rn(b0h, b1h), hD1 = __floats2half2_rn(b2h, b3h);
            *(ull*)&Hs[(pl0+0)*384 + d*12 + g4*4] = ((ull)*(unsigned*)&hA1 << 32) | *(unsigned*)&hA0;
            *(ull*)&Hs[(pl0+1)*384 + d*12 + g4*4] = ((ull)*(unsigned*)&hB1 << 32) | *(unsigned*)&hB0;
            *(ull*)&Hs[(pl0+2)*384 + d*12 + g4*4] = ((ull)*(unsigned*)&hC1 << 32) | *(unsigned*)&hC0;
            *(ull*)&Hs[(pl0+3)*384 + d*12 + g4*4] = ((ull)*(unsigned*)&hD1 << 32) | *(unsigned*)&hD0;
        }
    }

    if (k < 12) {
        __syncthreads();
        // dense write-out: 32 rows x 768B, coalesced uint4
        const uint4* hsrc = (const uint4*)Hs;
        uint4* dst = (uint4*)g_KAH2;
        int kbase = k * 48;             // uint4 offset within point row (576/pt)
        for (int i = tid; i < 1536; i += 256) {
            int pl = i / 48, off = i % 48;
            dst[(size_t)(p0 + pl)*576 + kbase + off] = hsrc[pl*48 + off];
        }
    }
}

// ---------------- kernel 3: theta + gather + max_n + sum_k + center -------
// block = 4 points x 96 (d,rg); k0/k1 fused via negation; parity-split max
__global__ void __launch_bounds__(384, 2) k_final(const int* __restrict__ nbr,
                                                  const float* __restrict__ verts,
                                                  float* __restrict__ out) {
    __shared__ float nds[4][32];
    __shared__ int qoffs[4][10];
    int tid = threadIdx.x;
    if (tid < 40) {
        int pp2 = tid / 10, n = tid % 10;
        int p2 = blockIdx.x*4 + pp2;
        int q = nbr[p2*10 + n];
        qoffs[pp2][n] = q * 9216;
        float dx = verts[q*3+0] - verts[p2*3+0];
        float dy = verts[q*3+1] - verts[p2*3+1];
        float dz = verts[q*3+2] - verts[p2*3+2];
        float nrm = sqrtf(dx*dx + dy*dy + dz*dz);
        float inv = 1.f / fmaxf(nrm, 1e-12f);
        nds[pp2][n*3+0] = dx*inv;
        nds[pp2][n*3+1] = dy*inv;
        nds[pp2][n*3+2] = dz*inv;
    }
    __syncthreads();
    int pp = tid / 96;
    int u  = tid % 96;
    int d  = u / 3, rg = u % 3;
    int p  = blockIdx.x*4 + pp;

    int qb[10];
#pragma unroll
    for (int n = 0; n < 10; n++) qb[n] = qoffs[pp][n];
    const float* ndp = nds[pp];

    float4 a4 = ((const float4*)&g_CEN[((size_t)d*2048 + p)*12])[rg];
    float acc0 = a4.x, acc1 = a4.y, acc2 = a4.z, acc3 = a4.w;

    const char* base = ((const char*)g_KAH2) + (size_t)d*24 + rg*8;
    const __half2 zero2 = __half2half2(__ushort_as_half(0));

    // ---- k = 0 & 1 fused: kdnt[1] == -kdnt[0] exactly ----
    {
        const float* ktb = &g_KDNT[d*12 + rg*4];
        float4 c0 = __ldg((const float4*)(ktb + 0));
        float4 c1 = __ldg((const float4*)(ktb + 384));
        float4 c2 = __ldg((const float4*)(ktb + 768));

        __half2 m01a, m23a;   // k=0 max
        __half2 m01b, m23b;   // k=1 max
#pragma unroll
        for (int n = 0; n < 10; n++) {
            float nx = ndp[n*3+0], ny = ndp[n*3+1], nz = ndp[n*3+2];
            float t0 = fmaf(c0.x, nx, fmaf(c1.x, ny, c2.x*nz));
            float t1 = fmaf(c0.y, nx, fmaf(c1.y, ny, c2.y*nz));
            float t2 = fmaf(c0.z, nx, fmaf(c1.z, ny, c2.z*nz));
            float t3 = fmaf(c0.w, nx, fmaf(c1.w, ny, c2.w*nz));
            __half2 t01 = __floats2half2_rn(t0, t1);
            __half2 t23 = __floats2half2_rn(t2, t3);
            __half2 h01p = __hmax2(t01, zero2);
            __half2 h23p = __hmax2(t23, zero2);
            __half2 h01n = __hmax2(__hneg2(t01), zero2);
            __half2 h23n = __hmax2(__hneg2(t23), zero2);
            uint2 g0 = *(const uint2*)(base + qb[n]);        // k=0
            uint2 g1 = *(const uint2*)(base + 768 + qb[n]);  // k=1
            __half2 v01a = __hmul2(h01p, *(__half2*)&g0.x);
            __half2 v23a = __hmul2(h23p, *(__half2*)&g0.y);
            __half2 v01b = __hmul2(h01n, *(__half2*)&g1.x);
            __half2 v23b = __hmul2(h23n, *(__half2*)&g1.y);
            if (n == 0) { m01a = v01a; m23a = v23a; m01b = v01b; m23b = v23b; }
            else {
                m01a = __hmax2(m01a, v01a); m23a = __hmax2(m23a, v23a);
                m01b = __hmax2(m01b, v01b); m23b = __hmax2(m23b, v23b);
            }
        }
        float2 fa = __half22float2(m01a);
        float2 fb = __half22float2(m23a);
        float2 fc = __half22float2(m01b);
        float2 fd = __half22float2(m23b);
        acc0 += fa.x + fc.x; acc1 += fa.y + fc.y;
        acc2 += fb.x + fd.x; acc3 += fb.y + fd.y;
    }

    // ---- k = 2..11 with parity-split max accumulators ----
#pragma unroll 1
    for (int k = 2; k < 12; k++) {
        const float* ktb = &g_KDNT[k*1152 + d*12 + rg*4];
        float4 c0 = __ldg((const float4*)(ktb + 0));
        float4 c1 = __ldg((const float4*)(ktb + 384));
        float4 c2 = __ldg((const float4*)(ktb + 768));
        const char* kbase = base + k*768;

        __half2 m01a, m23a, m01b, m23b;
#pragma unroll
        for (int n = 0; n < 10; n++) {
            float nx = ndp[n*3+0], ny = ndp[n*3+1], nz = ndp[n*3+2];
            float t0 = fmaf(c0.x, nx, fmaf(c1.x, ny, c2.x*nz));
            float t1 = fmaf(c0.y, nx, fmaf(c1.y, ny, c2.y*nz));
            float t2 = fmaf(c0.z, nx, fmaf(c1.z, ny, c2.z*nz));
            float t3 = fmaf(c0.w, nx, fmaf(c1.w, ny, c2.w*nz));
            __half2 h01 = __hmax2(__floats2half2_rn(t0, t1), zero2);
            __half2 h23 = __hmax2(__floats2half2_rn(t2, t3), zero2);
            uint2 g = *(const uint2*)(kbase + qb[n]);
            __half2 v01 = __hmul2(h01, *(__half2*)&g.x);
            __half2 v23 = __hmul2(h23, *(__half2*)&g.y);
            if (n == 0)      { m01a = v01; m23a = v23; }
            else if (n == 1) { m01b = v01; m23b = v23; }
            else if (n & 1)  { m01b = __hmax2(m01b, v01); m23b = __hmax2(m23b, v23); }
            else             { m01a = __hmax2(m01a, v01); m23a = __hmax2(m23a, v23); }
        }
        __half2 m01 = __hmax2(m01a, m01b);
        __half2 m23 = __hmax2(m23a, m23b);
        float2 f01 = __half22float2(m01);
        float2 f23 = __half22float2(m23);
        acc0 += f01.x; acc1 += f01.y;
        acc2 += f23.x; acc3 += f23.y;
    }
    ((float4*)&out[((size_t)d*2048 + p)*12])[rg] = make_float4(acc0, acc1, acc2, acc3);
}

// ---------------- launch ----------------------------------------------------
extern "C" void kernel_launch(void* const* d_in, const int* in_sizes, int n_in,
                              void* d_out, int out_size) {
    const int*   nbr   = (const int*)d_in[0];
    const float* verts = (const float*)d_in[1];
    const float* fmap  = (const float*)d_in[2];
    const float* W     = (const float*)d_in[3];
    const float* bias  = (const float*)d_in[4];
    const float* dirs  = (const float*)d_in[5];
    const float* fcw   = (const float*)d_in[6];
    float* out    = (float*)d_out;              // (1,32,2048,12)
    float* fm_out = out + 32*2048*12;           // (1,32,2048,3)

    k_fmprep<<<328, 256>>>(fmap, fcw, W, bias, dirs, fm_out);
    k_ka<<<dim3(13, 64), 256>>>();
    k_final<<<512, 384>>>(nbr, verts, out);
}

// round 13
// speedup vs baseline: 1.1368x; 1.0999x over previous
#include <cuda_runtime.h>
#include <cuda_fp16.h>
#include <math.h>
#include <float.h>

// B=1, C_IN=32, D_OUT=32, P=2048, N=10, A=12
typedef unsigned long long ull;

// ---------------- packed f32x2 helpers (sm_103a) ---------------------------
__device__ __forceinline__ ull f2pk(float lo, float hi) {
    ull r; asm("mov.b64 %0,{%1,%2};" : "=l"(r) : "f"(lo), "f"(hi)); return r;
}
__device__ __forceinline__ void f2up(ull v, float& lo, float& hi) {
    asm("mov.b64 {%0,%1},%2;" : "=f"(lo), "=f"(hi) : "l"(v));
}
__device__ __forceinline__ ull ffma2(ull a, ull b, ull c) {
    ull d; asm("fma.rn.f32x2 %0,%1,%2,%3;" : "=l"(d) : "l"(a), "l"(b), "l"(c)); return d;
}

// ---------------- device scratch ------------------------------------------
__device__ float g_ICO[108];                    // VER[r][i][j] floats (for k_ka)
__device__ __half g_KDNTH[12 * 3 * 32 * 12];    // [k][i][d][r] half
__device__ float g_W2[416 * 96];                // [dk][c*3+j]
__device__ float g_BIASF[416];                  // [dk]
__device__ float g_FMP[1024 * 192];             // [pair][c*3+i][2]  (pair = p>>1)
__device__ __half g_KAH2[2048 * 12 * 32 * 12];  // [q][k][d][r]  fp16, 18.9MB
__device__ float g_CEN[32 * 2048 * 12];         // [d][p][r] center (k==12), fp32

// ---------------- icosa constants: FP64, sqrt-only (no trig) ---------------
__device__ __forceinline__ void icosa_vertex(int r, double* u) {
    const double phi = (1.0 + sqrt(5.0)) * 0.5;
    int ia = r / 6, ib = (r / 3) % 2, t = r % 3;
    double a = ia ? -1.0 : 1.0;
    double b = ib ? -phi : phi;
    double v0, v1, v2;
    if (t == 0)      { v0 = 0.0; v1 = a;   v2 = b; }
    else if (t == 1) { v0 = a;   v1 = b;   v2 = 0.0; }
    else             { v0 = b;   v1 = 0.0; v2 = a; }
    double inv = 1.0 / sqrt(v0*v0 + v1*v1 + v2*v2);
    u[0] = v0*inv; u[1] = v1*inv; u[2] = v2*inv;
}
__device__ __forceinline__ double cos5(int m) {
    const double c1 = 0.30901699437494745;   // cos 72
    const double c2 = -0.8090169943749475;   // cos 144
    return (m == 0) ? 1.0 : (m == 1 || m == 4) ? c1 : c2;
}
__device__ __forceinline__ double sin5(int m) {
    const double s1 = 0.9510565162951535;    // sin 72
    const double s2 = 0.5877852522924731;    // sin 144
    return (m == 0) ? 0.0 : (m == 1) ? s1 : (m == 2) ? s2 : (m == 3) ? -s2 : -s1;
}
__device__ __forceinline__ float ver_elem(int tid) {
    int r = tid / 9, e = tid % 9, i = e / 3, j = e % 3;
    double u[3]; icosa_vertex(r, u);
    double c = u[2];
    double axx = -u[1], axy = u[0];
    double s = sqrt(axx*axx + axy*axy);
    double R[3][3];
    if (s < 1e-9) {
        for (int a = 0; a < 3; a++) for (int b = 0; b < 3; b++) R[a][b] = 0.0;
        R[0][0] = 1.0; R[1][1] = (c > 0) ? 1.0 : -1.0; R[2][2] = (c > 0) ? 1.0 : -1.0;
    } else {
        double kx = axx / s, ky = axy / s;
        double K[3][3] = {{0, 0, ky}, {0, 0, -kx}, {-ky, kx, 0}};
        double KK[3][3];
        for (int a = 0; a < 3; a++)
            for (int b = 0; b < 3; b++) {
                double acc = 0.0;
                for (int q = 0; q < 3; q++) acc += K[a][q]*K[q][b];
                KK[a][b] = acc;
            }
        for (int a = 0; a < 3; a++)
            for (int b = 0; b < 3; b++)
                R[a][b] = (a == b ? 1.0 : 0.0) + s*K[a][b] + (1.0 - c)*KK[a][b];
    }
    return (float)R[i][j];
}

// ---------------- kernel 1: fused fm (blocks 0-255) + weight prep (256-327)
__global__ void __launch_bounds__(256) k_fmprep(const float* __restrict__ fmap,
                                                const float* __restrict__ fcw,
                                                const float* __restrict__ W,
                                                const float* __restrict__ bias,
                                                const float* __restrict__ dirs,
                                                float* __restrict__ fm_out) {
    int tid = threadIdx.x;
    if (blockIdx.x < 256) {
        // ---- fm path: 8 warps x 1 point each ----
        __shared__ float FCT[32*33];
        __shared__ float Xs[8][384];
        __shared__ float VSs[36];
        int w = tid >> 5, lane = tid & 31;
        int p = blockIdx.x*8 + w;
        const float4* src = (const float4*)&fmap[((size_t)lane*2048 + p)*12];
        float4 x0 = src[0], x1 = src[1], x2 = src[2];
        for (int i = tid; i < 1024; i += 256) {
            int r = i >> 5, cc = i & 31;
            FCT[cc*33 + r] = fcw[i];
        }
        if (tid < 12) {
            double u[3]; icosa_vertex(tid, u);
            VSs[tid*3+0] = (float)u[0];
            VSs[tid*3+1] = (float)u[1];
            VSs[tid*3+2] = (float)u[2];
        }
        Xs[w][0*32+lane] = x0.x;  Xs[w][1*32+lane]  = x0.y;
        Xs[w][2*32+lane] = x0.z;  Xs[w][3*32+lane]  = x0.w;
        Xs[w][4*32+lane] = x1.x;  Xs[w][5*32+lane]  = x1.y;
        Xs[w][6*32+lane] = x1.z;  Xs[w][7*32+lane]  = x1.w;
        Xs[w][8*32+lane] = x2.x;  Xs[w][9*32+lane]  = x2.y;
        Xs[w][10*32+lane] = x2.z; Xs[w][11*32+lane] = x2.w;
        __syncthreads();

        float L[12];
#pragma unroll
        for (int a = 0; a < 12; a++) L[a] = 0.f;
#pragma unroll
        for (int cc = 0; cc < 32; cc++) {
            float fc = FCT[cc*33 + lane];
#pragma unroll
            for (int a = 0; a < 12; a++) L[a] += Xs[w][a*32+cc] * fc;
        }
        float mx = L[0];
#pragma unroll
        for (int a = 1; a < 12; a++) mx = fmaxf(mx, L[a]);
        float e[12], s = 0.f;
#pragma unroll
        for (int a = 0; a < 12; a++) { e[a] = expf(L[a] - mx); s += e[a]; }
        float inv = 1.f / s;
        float f0 = 0.f, f1 = 0.f, f2 = 0.f;
#pragma unroll
        for (int a = 0; a < 12; a++) {
            float y = e[a] * inv * Xs[w][a*32+lane];
            f0 += y * VSs[a*3+0];
            f1 += y * VSs[a*3+1];
            f2 += y * VSs[a*3+2];
        }
        float* fp = &g_FMP[((size_t)(p >> 1)*96 + lane*3)*2 + (p & 1)];
        fp[0] = f0; fp[2] = f1; fp[4] = f2;
        fm_out[((size_t)lane*2048 + p)*3 + 0] = f0;
        fm_out[((size_t)lane*2048 + p)*3 + 1] = f1;
        fm_out[((size_t)lane*2048 + p)*3 + 2] = f2;
    } else {
        // ---- weight prep path ----
        __shared__ float SYMR[45];
        __shared__ float VER[108];
        int t = (blockIdx.x - 256) * 256 + tid;
        float pre[3]; pre[0] = pre[1] = pre[2] = 0.f;
        float preBias = 0.f;
        if (t < 4608) {
            int d = t / 144, k = (t / 12) % 12;
            if (k >= 2) {
                int kk = (k - 2) / 5;
                pre[0] = dirs[d*6 + kk*3 + 0];
                pre[1] = dirs[d*6 + kk*3 + 1];
                pre[2] = dirs[d*6 + kk*3 + 2];
            }
        } else if (t < 4608 + 13312) {
            int id = t - 4608;
            int dk = id / 32, c = id % 32;
            int d = dk / 13, k = dk % 13;
            const float* wr = W + (d*32 + c)*9;
            if (k == 0)       pre[0] = wr[0];
            else if (k == 1)  pre[0] = wr[1];
            else if (k == 12) pre[0] = wr[8];
            else {
                int kk = (k - 2) / 5;
                pre[0] = wr[2 + kk*3 + 0];
                pre[1] = wr[2 + kk*3 + 1];
                pre[2] = wr[2 + kk*3 + 2];
            }
        } else if (t < 4608 + 13312 + 416) {
            int dk = t - (4608 + 13312);
            int d = dk / 13, k = dk % 13;
            int col = (k == 0) ? 0 : (k == 1) ? 1 : (k <= 6) ? 2 : (k <= 11) ? 3 : 4;
            preBias = bias[d*5 + col];
        }
        if (tid < 45) {
            int m = tid / 9, e = tid % 9, i = e / 3, j = e % 3;
            double ct = cos5(m), st = sin5(m);
            double R[3][3] = {{ct, -st, 0.0}, {st, ct, 0.0}, {0.0, 0.0, 1.0}};
            SYMR[tid] = (float)R[i][j];
        }
        if (tid < 108) {
            float v = ver_elem(tid);
            VER[tid] = v;
            if (blockIdx.x == 256) g_ICO[tid] = v;   // publish for k_ka
        }
        __syncthreads();
        if (t < 4608) {
            int d = t / 144, k = (t / 12) % 12, r = t % 12;
            float vv[3];
            if (k == 0)      { vv[0] = 0.f; vv[1] = 0.f; vv[2] = 1.f; }
            else if (k == 1) { vv[0] = 0.f; vv[1] = 0.f; vv[2] = -1.f; }
            else {
                int m = (k - 2) % 5;
                float d0 = pre[0], d1 = pre[1], d2 = pre[2];
                float nrm = sqrtf(d0*d0 + d1*d1 + d2*d2);
                float inv = 1.f / fmaxf(nrm, 1e-12f);
                d0 *= inv; d1 *= inv; d2 *= inv;
                for (int i = 0; i < 3; i++)
                    vv[i] = SYMR[m*9+i*3+0]*d0 + SYMR[m*9+i*3+1]*d1 + SYMR[m*9+i*3+2]*d2;
            }
            for (int i = 0; i < 3; i++) {
                float o = VER[r*9+i*3+0]*vv[0] + VER[r*9+i*3+1]*vv[1] + VER[r*9+i*3+2]*vv[2];
                g_KDNTH[((k*3 + i)*32 + d)*12 + r] = __float2half_rn(o);
            }
        } else if (t < 4608 + 13312) {
            int id = t - 4608;
            int dk = id / 32, c = id % 32;
            int k = dk % 13;
            float wf[3];
            if (k == 0)       { wf[0] = 0.f; wf[1] = 0.f; wf[2] = pre[0]; }
            else if (k == 1)  { wf[0] = 0.f; wf[1] = 0.f; wf[2] = -pre[0]; }
            else if (k == 12) { wf[0] = 0.f; wf[1] = 0.f; wf[2] = pre[0]; }
            else {
                int m = (k - 2) % 5;
                for (int i = 0; i < 3; i++)
                    wf[i] = SYMR[m*9+i*3+0]*pre[0] + SYMR[m*9+i*3+1]*pre[1] + SYMR[m*9+i*3+2]*pre[2];
            }
            g_W2[dk*96 + c*3 + 0] = wf[0];
            g_W2[dk*96 + c*3 + 1] = wf[1];
            g_W2[dk*96 + c*3 + 2] = wf[2];
        } else if (t < 4608 + 13312 + 416) {
            int dk = t - (4608 + 13312);
            g_BIASF[dk] = preBias;
        }
    }
}

// ---------------- kernel 2: ka — one k x 32 d x 32 p per block -------------
// 256 thr = 32 d x 8 ps; NO min-blocks clause (avoid register spills)
__global__ void __launch_bounds__(256) k_ka() {
    __shared__ float  Ws[32*97];    // [d][c*3+j]
    __shared__ ull    Fp[16][98];   // [pair][c*3+i] = {fm[even], fm[odd]}
    __shared__ float2 verd[108];
    __shared__ float2 biasd[32];
    __shared__ __half Hs[32*384];   // [pl][d*12+r]  768B per point row
    int k  = blockIdx.x;            // 0..12
    int p0 = blockIdx.y * 32;
    int tid = threadIdx.x;

    for (int i = tid; i < 32*96; i += 256) {
        int dd = i / 96, q = i % 96;
        Ws[dd*97 + q] = g_W2[(dd*13 + k)*96 + q];
    }
    {
        const float4* src = (const float4*)&g_FMP[(size_t)(p0 >> 1) * 192];
        for (int i = tid; i < 16*48; i += 256)
            ((float4*)&Fp[i / 48][0])[i % 48] = src[i];
    }
    if (tid < 108) { float v = g_ICO[tid]; verd[tid] = make_float2(v, v); }
    if (tid < 32)  { float bv = g_BIASF[tid*13 + k]; biasd[tid] = make_float2(bv, bv); }
    __syncthreads();

    int d  = tid & 31;
    int ps = tid >> 5;              // 0..7: pairs 2ps, 2ps+1 = points p0+4ps..+3
    const float* wrow = &Ws[d*97];
    const ull* fA = Fp[2*ps];
    const ull* fB = Fp[2*ps + 1];

    ull GA[9], GB[9];
#pragma unroll
    for (int q = 0; q < 9; q++) { GA[q] = 0ULL; GB[q] = 0ULL; }

#pragma unroll 4
    for (int cp = 0; cp < 16; cp++) {   // c = 2cp, 2cp+1
        float we0 = wrow[6*cp+0], we1 = wrow[6*cp+1], we2 = wrow[6*cp+2];
        float wo0 = wrow[6*cp+3], wo1 = wrow[6*cp+4], wo2 = wrow[6*cp+5];
        ull We0 = f2pk(we0, we0), We1 = f2pk(we1, we1), We2 = f2pk(we2, we2);
        ull Wo0 = f2pk(wo0, wo0), Wo1 = f2pk(wo1, wo1), Wo2 = f2pk(wo2, wo2);
        ulonglong2 aA = *(const ulonglong2*)&fA[6*cp];       // f0e, f1e
        ulonglong2 aB = *(const ulonglong2*)&fA[6*cp+2];     // f2e, f0o
        ulonglong2 aC = *(const ulonglong2*)&fA[6*cp+4];     // f1o, f2o
        ulonglong2 bA = *(const ulonglong2*)&fB[6*cp];
        ulonglong2 bB = *(const ulonglong2*)&fB[6*cp+2];
        ulonglong2 bC = *(const ulonglong2*)&fB[6*cp+4];
        // even c
        GA[0] = ffma2(We0, aA.x, GA[0]); GA[1] = ffma2(We0, aA.y, GA[1]); GA[2] = ffma2(We0, aB.x, GA[2]);
        GA[3] = ffma2(We1, aA.x, GA[3]); GA[4] = ffma2(We1, aA.y, GA[4]); GA[5] = ffma2(We1, aB.x, GA[5]);
        GA[6] = ffma2(We2, aA.x, GA[6]); GA[7] = ffma2(We2, aA.y, GA[7]); GA[8] = ffma2(We2, aB.x, GA[8]);
        GB[0] = ffma2(We0, bA.x, GB[0]); GB[1] = ffma2(We0, bA.y, GB[1]); GB[2] = ffma2(We0, bB.x, GB[2]);
        GB[3] = ffma2(We1, bA.x, GB[3]); GB[4] = ffma2(We1, bA.y, GB[4]); GB[5] = ffma2(We1, bB.x, GB[5]);
        GB[6] = ffma2(We2, bA.x, GB[6]); GB[7] = ffma2(We2, bA.y, GB[7]); GB[8] = ffma2(We2, bB.x, GB[8]);
        // odd c
        GA[0] = ffma2(Wo0, aB.y, GA[0]); GA[1] = ffma2(Wo0, aC.x, GA[1]); GA[2] = ffma2(Wo0, aC.y, GA[2]);
        GA[3] = ffma2(Wo1, aB.y, GA[3]); GA[4] = ffma2(Wo1, aC.x, GA[4]); GA[5] = ffma2(Wo1, aC.y, GA[5]);
        GA[6] = ffma2(Wo2, aB.y, GA[6]); GA[7] = ffma2(Wo2, aC.x, GA[7]); GA[8] = ffma2(Wo2, aC.y, GA[8]);
        GB[0] = ffma2(Wo0, bB.y, GB[0]); GB[1] = ffma2(Wo0, bC.x, GB[1]); GB[2] = ffma2(Wo0, bC.y, GB[2]);
        GB[3] = ffma2(Wo1, bB.y, GB[3]); GB[4] = ffma2(Wo1, bC.x, GB[4]); GB[5] = ffma2(Wo1, bC.y, GB[5]);
        GB[6] = ffma2(Wo2, bB.y, GB[6]); GB[7] = ffma2(Wo2, bC.x, GB[7]); GB[8] = ffma2(Wo2, bC.y, GB[8]);
    }

    ull bias2 = *(const ull*)&biasd[d];
    int pl0 = ps*4;                 // pair A -> points pl0, pl0+1; pair B -> +2,+3

#pragma unroll
    for (int g4 = 0; g4 < 3; g4++) {
        ull oA[4], oB[4];
#pragma unroll
        for (int rr = 0; rr < 4; rr++) {
            int r = g4*4 + rr;
            ull sA = bias2, sB = bias2;
#pragma unroll
            for (int i = 0; i < 3; i++)
#pragma unroll
                for (int j = 0; j < 3; j++) {
                    ull v = *(const ull*)&verd[r*9 + i*3 + j];
                    sA = ffma2(v, GA[j*3 + i], sA);
                    sB = ffma2(v, GB[j*3 + i], sB);
                }
            oA[rr] = sA; oB[rr] = sB;
        }
        float a0l,a0h,a1l,a1h,a2l,a2h,a3l,a3h;
        float b0l,b0h,b1l,b1h,b2l,b2h,b3l,b3h;
        f2up(oA[0], a0l, a0h); f2up(oA[1], a1l, a1h);
        f2up(oA[2], a2l, a2h); f2up(oA[3], a3l, a3h);
        f2up(oB[0], b0l, b0h); f2up(oB[1], b1l, b1h);
        f2up(oB[2], b2l, b2h); f2up(oB[3], b3l, b3h);
        if (k == 12) {
            *(float4*)&g_CEN[((size_t)d*2048 + p0 + pl0 + 0)*12 + g4*4] = make_float4(a0l, a1l, a2l, a3l);
            *(float4*)&g_CEN[((size_t)d*2048 + p0 + pl0 + 1)*12 + g4*4] = make_float4(a0h, a1h, a2h, a3h);
            *(float4*)&g_CEN[((size_t)d*2048 + p0 + pl0 + 2)*12 + g4*4] = make_float4(b0l, b1l, b2l, b3l);
            *(float4*)&g_CEN[((size_t)d*2048 + p0 + pl0 + 3)*12 + g4*4] = make_float4(b0h, b1h, b2h, b3h);
        } else {
            __half2 hA0 = __floats2half2_rn(a0l, a1l), hA1 = __floats2half2_rn(a2l, a3l);
            __half2 hB0 = __floats2half2_rn(a0h, a1h), hB1 = __floats2half2_rn(a2h, a3h);
            __half2 hC0 = __floats2half2_rn(b0l, b1l), hC1 = __floats2half2_rn(b2l, b3l);
            __half2 hD0 = __floats2half2_rn(b0h, b1h), hD1 = __floats2half2_rn(b2h, b3h);
            *(ull*)&Hs[(pl0+0)*384 + d*12 + g4*4] = ((ull)*(unsigned*)&hA1 << 32) | *(unsigned*)&hA0;
            *(ull*)&Hs[(pl0+1)*384 + d*12 + g4*4] = ((ull)*(unsigned*)&hB1 << 32) | *(unsigned*)&hB0;
            *(ull*)&Hs[(pl0+2)*384 + d*12 + g4*4] = ((ull)*(unsigned*)&hC1 << 32) | *(unsigned*)&hC0;
            *(ull*)&Hs[(pl0+3)*384 + d*12 + g4*4] = ((ull)*(unsigned*)&hD1 << 32) | *(unsigned*)&hD0;
        }
    }

    if (k < 12) {
        __syncthreads();
        // dense write-out: 32 rows x 768B, coalesced uint4
        const uint4* hsrc = (const uint4*)Hs;
        uint4* dst = (uint4*)g_KAH2;
        int kbase = k * 48;             // uint4 offset within point row (576/pt)
        for (int i = tid; i < 1536; i += 256) {
            int pl = i / 48, off = i % 48;
            dst[(size_t)(p0 + pl)*576 + kbase + off] = hsrc[pl*48 + off];
        }
    }
}

// ---------------- kernel 3: theta + gather + max_n + sum_k + center -------
// block = 4 points x 96 (d,rg); theta fully in half2 (HFMA2 chain)
__global__ void __launch_bounds__(384, 2) k_final(const int* __restrict__ nbr,
                                                  const float* __restrict__ verts,
                                                  float* __restrict__ out) {
    __shared__ unsigned ndh[4][32];   // [pp][n*3+i] dup half2 (30 used)
    __shared__ int qoffs[4][10];
    int tid = threadIdx.x;
    if (tid < 40) {
        int pp2 = tid / 10, n = tid % 10;
        int p2 = blockIdx.x*4 + pp2;
        int q = nbr[p2*10 + n];
        qoffs[pp2][n] = q * 9216;
        float dx = verts[q*3+0] - verts[p2*3+0];
        float dy = verts[q*3+1] - verts[p2*3+1];
        float dz = verts[q*3+2] - verts[p2*3+2];
        float nrm = sqrtf(dx*dx + dy*dy + dz*dz);
        float inv = 1.f / fmaxf(nrm, 1e-12f);
        __half2 h0 = __half2half2(__float2half_rn(dx*inv));
        __half2 h1 = __half2half2(__float2half_rn(dy*inv));
        __half2 h2 = __half2half2(__float2half_rn(dz*inv));
        ndh[pp2][n*3+0] = *(unsigned*)&h0;
        ndh[pp2][n*3+1] = *(unsigned*)&h1;
        ndh[pp2][n*3+2] = *(unsigned*)&h2;
    }
    __syncthreads();
    int pp = tid / 96;
    int u  = tid % 96;
    int d  = u / 3, rg = u % 3;
    int p  = blockIdx.x*4 + pp;

    int qb[10];
#pragma unroll
    for (int n = 0; n < 10; n++) qb[n] = qoffs[pp][n];
    const unsigned* ndp = ndh[pp];

    float4 a4 = ((const float4*)&g_CEN[((size_t)d*2048 + p)*12])[rg];
    float acc0 = a4.x, acc1 = a4.y, acc2 = a4.z, acc3 = a4.w;

    const char* base = ((const char*)g_KAH2) + (size_t)d*24 + rg*8;
    const __half2 zero2 = __half2half2(__ushort_as_half(0));

#pragma unroll 1
    for (int k = 0; k < 12; k++) {
        const __half* kth = &g_KDNTH[k*1152 + d*12 + rg*4];
        uint2 ci0 = __ldg((const uint2*)(kth + 0));     // i=0: (r0,r1),(r2,r3)
        uint2 ci1 = __ldg((const uint2*)(kth + 384));   // i=1
        uint2 ci2 = __ldg((const uint2*)(kth + 768));   // i=2
        __half2 c0_01 = *(__half2*)&ci0.x, c0_23 = *(__half2*)&ci0.y;
        __half2 c1_01 = *(__half2*)&ci1.x, c1_23 = *(__half2*)&ci1.y;
        __half2 c2_01 = *(__half2*)&ci2.x, c2_23 = *(__half2*)&ci2.y;
        const char* kbase = base + k*768;

        __half2 m01, m23;
#pragma unroll
        for (int n = 0; n < 10; n++) {
            unsigned u0 = ndp[n*3+0], u1 = ndp[n*3+1], u2 = ndp[n*3+2];
            __half2 n0 = *(__half2*)&u0, n1 = *(__half2*)&u1, n2 = *(__half2*)&u2;
            __half2 t01 = __hfma2(c0_01, n0, __hfma2(c1_01, n1, __hmul2(c2_01, n2)));
            __half2 t23 = __hfma2(c0_23, n0, __hfma2(c1_23, n1, __hmul2(c2_23, n2)));
            __half2 h01 = __hmax2(t01, zero2);
            __half2 h23 = __hmax2(t23, zero2);
            uint2 g = *(const uint2*)(kbase + qb[n]);
            __half2 v01 = __hmul2(h01, *(__half2*)&g.x);
            __half2 v23 = __hmul2(h23, *(__half2*)&g.y);
            if (n == 0) { m01 = v01; m23 = v23; }
            else        { m01 = __hmax2(m01, v01); m23 = __hmax2(m23, v23); }
        }
        float2 f01 = __half22float2(m01);
        float2 f23 = __half22float2(m23);
        acc0 += f01.x; acc1 += f01.y;
        acc2 += f23.x; acc3 += f23.y;
    }
    ((float4*)&out[((size_t)d*2048 + p)*12])[rg] = make_float4(acc0, acc1, acc2, acc3);
}

// ---------------- launch ----------------------------------------------------
extern "C" void kernel_launch(void* const* d_in, const int* in_sizes, int n_in,
                              void* d_out, int out_size) {
    const int*   nbr   = (const int*)d_in[0];
    const float* verts = (const float*)d_in[1];
    const float* fmap  = (const float*)d_in[2];
    const float* W     = (const float*)d_in[3];
    const float* bias  = (const float*)d_in[4];
    const float* dirs  = (const float*)d_in[5];
    const float* fcw   = (const float*)d_in[6];
    float* out    = (float*)d_out;              // (1,32,2048,12)
    float* fm_out = out + 32*2048*12;           // (1,32,2048,3)

    k_fmprep<<<328, 256>>>(fmap, fcw, W, bias, dirs, fm_out);
    k_ka<<<dim3(13, 64), 256>>>();
    k_final<<<512, 384>>>(nbr, verts, out);
}